// round 11
// baseline (speedup 1.0000x reference)
#include <cuda_runtime.h>
#include <cuda_bf16.h>
#include <math.h>

// Problem dims
#define NL  2
#define NB  2
#define T_  2048
#define C_  512
#define H_  8
#define FF_ 1024
#define HS_ 64
#define EPS_ 1.1920929e-07f

#define BT_  (NB * T_)        // 4096 rows
#define BTC_ (NB * T_ * C_)   // 2097152
#define BH_  (NB * H_)        // 16

// ---------------- scratch ----------------
__device__ __nv_bfloat16 g_xnb[BTC_];    // bf16 normed activations
__device__ __nv_bfloat16 g_hnb[BTC_];
__device__ __nv_bfloat16 g_q[BTC_];      // [B,H,T,HS] bf16
__device__ __nv_bfloat16 g_k[BTC_];
__device__ __nv_bfloat16 g_v[BTC_];
__device__ __nv_bfloat16 g_attnb[BTC_];  // [B,T,C] bf16 (flash out)
__device__ __nv_bfloat16 g_ffb[NB * T_ * FF_];

// ---------------- cp.async helpers ----------------
__device__ __forceinline__ unsigned sm_u32(const void* p) {
    return (unsigned)__cvta_generic_to_shared(p);
}
__device__ __forceinline__ void cp16(void* dst_smem, const void* src) {
    asm volatile("cp.async.cg.shared.global [%0], [%1], 16;"
                 :: "r"(sm_u32(dst_smem)), "l"(src));
}
#define CP_COMMIT() asm volatile("cp.async.commit_group;")
#define CP_WAIT(n)  asm volatile("cp.async.wait_group %0;" :: "n"(n))

// ---------------- helpers ----------------
__global__ void copy_k(float4* __restrict__ dst, const float4* __restrict__ src, int n4) {
    int i = blockIdx.x * blockDim.x + threadIdx.x;
    if (i < n4) dst[i] = src[i];
}

// rmsnorm -> bf16 output
__global__ __launch_bounds__(256) void rmsnorm_k(
    const float* __restrict__ x, const float* __restrict__ g,
    __nv_bfloat16* __restrict__ outb)
{
    long row = blockIdx.x;
    const float* xr = x + row * C_;
    int tid = threadIdx.x;
    float v0 = xr[tid];
    float v1 = xr[tid + 256];
    float ss = v0 * v0 + v1 * v1;

    __shared__ float red[8];
    #pragma unroll
    for (int o = 16; o; o >>= 1) ss += __shfl_xor_sync(0xffffffffu, ss, o);
    if ((tid & 31) == 0) red[tid >> 5] = ss;
    __syncthreads();
    if (tid == 0) {
        float s = 0.f;
        #pragma unroll
        for (int w = 0; w < 8; w++) s += red[w];
        red[0] = rsqrtf(s * (1.0f / C_) + EPS_);
    }
    __syncthreads();
    float r = red[0];
    __nv_bfloat16* ob = outb + row * C_;
    ob[tid]       = __float2bfloat16_rn(v0 * r * g[tid]);
    ob[tid + 256] = __float2bfloat16_rn(v1 * r * g[tid + 256]);
}

// ---------------- mma helpers ----------------
__device__ __forceinline__ void mma_bf16(float* d, const unsigned* a, unsigned b0, unsigned b1) {
    asm volatile(
        "mma.sync.aligned.m16n8k16.row.col.f32.bf16.bf16.f32 "
        "{%0,%1,%2,%3}, {%4,%5,%6,%7}, {%8,%9}, {%0,%1,%2,%3};"
        : "+f"(d[0]), "+f"(d[1]), "+f"(d[2]), "+f"(d[3])
        : "r"(a[0]), "r"(a[1]), "r"(a[2]), "r"(a[3]), "r"(b0), "r"(b1));
}
__device__ __forceinline__ unsigned packbf(float lo, float hi) {
    unsigned d;
    asm("cvt.rn.bf16x2.f32 %0, %1, %2;" : "=r"(d) : "f"(hi), "f"(lo));
    return d;
}
__device__ __forceinline__ float ex2f(float x) {
    float y;
    asm("ex2.approx.f32 %0, %1;" : "=f"(y) : "f"(x));
    return y;
}

#define QASTR 40    // A smem row pitch (bf16): 32 + 8 pad
#define QBSTR 136   // B smem row pitch (bf16): 128 + 8 pad

// ---------------- bf16 QKV projection GEMM (head-blocked B and C) ----------------
// MI: m-blocks of 16 rows per warp; CTA rows = 32*MI (MI=4 ->128, MI=2 ->64).
template<int MI>
__global__ __launch_bounds__(256) void gemm_qkv_bf(
    const __nv_bfloat16* __restrict__ A,
    const float* __restrict__ B0, const float* __restrict__ B1, const float* __restrict__ B2,
    __nv_bfloat16* __restrict__ C0, __nv_bfloat16* __restrict__ C1, __nv_bfloat16* __restrict__ C2,
    int nColBlk)
{
    __shared__ __nv_bfloat16 As[2][32 * MI * QASTR];
    __shared__ __nv_bfloat16 Bs[2][32 * QBSTR];

    int sel  = blockIdx.x / nColBlk;
    int colb = blockIdx.x - sel * nColBlk;
    const float* B = (sel == 0) ? B0 : (sel == 1) ? B1 : B2;
    __nv_bfloat16* Cp = ((sel == 0) ? C0 : (sel == 1) ? C1 : C2)
                        + (long)blockIdx.z * H_ * T_ * HS_;

    const __nv_bfloat16* Ab = A + (long)blockIdx.z * T_ * C_ + (long)(blockIdx.y * 32 * MI) * C_;
    int col0 = colb * 128;

    int tid = threadIdx.x, lane = tid & 31, w = tid >> 5;
    int g = lane >> 2, t4 = lane & 3;
    int wm = w & 1, wn = w >> 1;

    float acc[MI][4][4];
    #pragma unroll
    for (int i = 0; i < MI; i++)
        #pragma unroll
        for (int j = 0; j < 4; j++)
            #pragma unroll
            for (int q = 0; q < 4; q++) acc[i][j][q] = 0.f;

    auto cpA = [&](int st, int k0) {
        #pragma unroll
        for (int j = 0; j < MI / 2; j++) {
            int c = tid * (MI / 2) + j;
            int row = c >> 2, kc = (c & 3) * 8;
            cp16(&As[st][row * QASTR + kc], Ab + (long)row * C_ + k0 + kc);
        }
    };

    int bk = tid >> 3;
    int bn0 = (tid & 7) * 16;
    float4 bp[4];
    auto ldB = [&](int k0) {
        #pragma unroll
        for (int jj = 0; jj < 4; jj++) {
            int gc = col0 + bn0 + jj * 4;
            bp[jj] = *reinterpret_cast<const float4*>(
                &B[(long)(gc >> 6) * C_ * HS_ + (long)(k0 + bk) * HS_ + (gc & 63)]);
        }
    };
    auto stB = [&](int st) {
        #pragma unroll
        for (int jj = 0; jj < 4; jj++) {
            uint2 u = { packbf(bp[jj].x, bp[jj].y), packbf(bp[jj].z, bp[jj].w) };
            *reinterpret_cast<uint2*>(&Bs[st][bk * QBSTR + bn0 + jj * 4]) = u;
        }
    };

    int a_lrow = lane & 15, a_lk = (lane >> 4) * 8;
    int b_lrow = ((lane >> 3) & 1) * 8 + (lane & 7), b_lc = (lane >> 4) * 8;

    cpA(0, 0); CP_COMMIT();
    ldB(0);

    #pragma unroll 1
    for (int kt = 0; kt < C_ / 32; kt++) {
        int s = kt & 1;
        CP_WAIT(0);
        stB(s);
        __syncthreads();
        if (kt + 1 < C_ / 32) {
            cpA(s ^ 1, (kt + 1) * 32);
            CP_COMMIT();
            ldB((kt + 1) * 32);
        }

        #pragma unroll
        for (int kc = 0; kc < 32; kc += 16) {
            unsigned afr[MI][4];
            #pragma unroll
            for (int mi = 0; mi < MI; mi++) {
                int m0 = wm * 16 * MI + mi * 16;
                unsigned addr = sm_u32(&As[s][(m0 + a_lrow) * QASTR + kc + a_lk]);
                asm volatile(
                    "ldmatrix.sync.aligned.m8n8.x4.shared.b16 {%0,%1,%2,%3}, [%4];"
                    : "=r"(afr[mi][0]), "=r"(afr[mi][1]), "=r"(afr[mi][2]), "=r"(afr[mi][3])
                    : "r"(addr));
            }
            #pragma unroll
            for (int gi = 0; gi < 2; gi++) {
                int n0 = wn * 32 + gi * 16;
                unsigned r0, r1, r2, r3;
                unsigned addr = sm_u32(&Bs[s][(kc + b_lrow) * QBSTR + n0 + b_lc]);
                asm volatile(
                    "ldmatrix.sync.aligned.m8n8.x4.trans.shared.b16 {%0,%1,%2,%3}, [%4];"
                    : "=r"(r0), "=r"(r1), "=r"(r2), "=r"(r3) : "r"(addr));
                #pragma unroll
                for (int mi = 0; mi < MI; mi++) {
                    mma_bf16(acc[mi][2 * gi],     afr[mi], r0, r1);
                    mma_bf16(acc[mi][2 * gi + 1], afr[mi], r2, r3);
                }
            }
        }
    }

    int row0 = blockIdx.y * 32 * MI;
    #pragma unroll
    for (int mi = 0; mi < MI; mi++) {
        #pragma unroll
        for (int ni = 0; ni < 4; ni++) {
            int r0 = row0 + wm * 16 * MI + mi * 16 + g;
            int c  = col0 + wn * 32 + ni * 8 + t4 * 2;
            long hb = (long)(c >> 6) * T_ * HS_ + (c & 63);
            #pragma unroll
            for (int half = 0; half < 2; half++) {
                int rr = r0 + half * 8;
                *reinterpret_cast<unsigned*>(&Cp[hb + (long)rr * HS_]) =
                    packbf(acc[mi][ni][half * 2 + 0], acc[mi][ni][half * 2 + 1]);
            }
        }
    }
}

// ---------------- bf16 dense GEMM (plain layouts): O-proj / FFN ----------------
template<int MI>
__global__ __launch_bounds__(256) void gemm_bf(
    int K,
    const __nv_bfloat16* __restrict__ A, int lda,
    const float* __restrict__ B, int ldb,
    const float* __restrict__ bias,
    float* __restrict__ Cf, __nv_bfloat16* __restrict__ Cb,
    int ldc, int accumulate, int gelu_act)
{
    __shared__ __nv_bfloat16 As[2][32 * MI * QASTR];
    __shared__ __nv_bfloat16 Bs[2][32 * QBSTR];

    int row0 = blockIdx.y * 32 * MI;
    int col0 = blockIdx.x * 128;

    int tid = threadIdx.x, lane = tid & 31, w = tid >> 5;
    int g = lane >> 2, t4 = lane & 3;
    int wm = w & 1, wn = w >> 1;

    float acc[MI][4][4];
    #pragma unroll
    for (int i = 0; i < MI; i++)
        #pragma unroll
        for (int j = 0; j < 4; j++)
            #pragma unroll
            for (int q = 0; q < 4; q++) acc[i][j][q] = 0.f;

    const __nv_bfloat16* Ab = A + (long)row0 * lda;

    auto cpA = [&](int st, int k0) {
        #pragma unroll
        for (int j = 0; j < MI / 2; j++) {
            int c = tid * (MI / 2) + j;
            int row = c >> 2, kc = (c & 3) * 8;
            cp16(&As[st][row * QASTR + kc], Ab + (long)row * lda + k0 + kc);
        }
    };

    int bk = tid >> 3;
    int bn0 = (tid & 7) * 16;
    float4 bp[4];
    auto ldB = [&](int k0) {
        #pragma unroll
        for (int jj = 0; jj < 4; jj++)
            bp[jj] = *reinterpret_cast<const float4*>(
                &B[(long)(k0 + bk) * ldb + col0 + bn0 + jj * 4]);
    };
    auto stB = [&](int st) {
        #pragma unroll
        for (int jj = 0; jj < 4; jj++) {
            uint2 u = { packbf(bp[jj].x, bp[jj].y), packbf(bp[jj].z, bp[jj].w) };
            *reinterpret_cast<uint2*>(&Bs[st][bk * QBSTR + bn0 + jj * 4]) = u;
        }
    };

    int a_lrow = lane & 15, a_lk = (lane >> 4) * 8;
    int b_lrow = ((lane >> 3) & 1) * 8 + (lane & 7), b_lc = (lane >> 4) * 8;

    cpA(0, 0); CP_COMMIT();
    ldB(0);

    int nK = K / 32;
    #pragma unroll 1
    for (int kt = 0; kt < nK; kt++) {
        int s = kt & 1;
        CP_WAIT(0);
        stB(s);
        __syncthreads();
        if (kt + 1 < nK) {
            cpA(s ^ 1, (kt + 1) * 32);
            CP_COMMIT();
            ldB((kt + 1) * 32);
        }

        #pragma unroll
        for (int kc = 0; kc < 32; kc += 16) {
            unsigned afr[MI][4];
            #pragma unroll
            for (int mi = 0; mi < MI; mi++) {
                int m0 = wm * 16 * MI + mi * 16;
                unsigned addr = sm_u32(&As[s][(m0 + a_lrow) * QASTR + kc + a_lk]);
                asm volatile(
                    "ldmatrix.sync.aligned.m8n8.x4.shared.b16 {%0,%1,%2,%3}, [%4];"
                    : "=r"(afr[mi][0]), "=r"(afr[mi][1]), "=r"(afr[mi][2]), "=r"(afr[mi][3])
                    : "r"(addr));
            }
            #pragma unroll
            for (int gi = 0; gi < 2; gi++) {
                int n0 = wn * 32 + gi * 16;
                unsigned r0, r1, r2, r3;
                unsigned addr = sm_u32(&Bs[s][(kc + b_lrow) * QBSTR + n0 + b_lc]);
                asm volatile(
                    "ldmatrix.sync.aligned.m8n8.x4.trans.shared.b16 {%0,%1,%2,%3}, [%4];"
                    : "=r"(r0), "=r"(r1), "=r"(r2), "=r"(r3) : "r"(addr));
                #pragma unroll
                for (int mi = 0; mi < MI; mi++) {
                    mma_bf16(acc[mi][2 * gi],     afr[mi], r0, r1);
                    mma_bf16(acc[mi][2 * gi + 1], afr[mi], r2, r3);
                }
            }
        }
    }

    #pragma unroll
    for (int mi = 0; mi < MI; mi++) {
        #pragma unroll
        for (int ni = 0; ni < 4; ni++) {
            int r0 = row0 + wm * 16 * MI + mi * 16 + g;
            int c  = col0 + wn * 32 + ni * 8 + t4 * 2;
            #pragma unroll
            for (int half = 0; half < 2; half++) {
                int rr = r0 + half * 8;
                float v0 = acc[mi][ni][half * 2 + 0];
                float v1 = acc[mi][ni][half * 2 + 1];
                if (bias) { v0 += bias[c]; v1 += bias[c + 1]; }
                if (gelu_act) {
                    v0 = 0.5f * v0 * (1.0f + erff(v0 * 0.70710678118654752f));
                    v1 = 0.5f * v1 * (1.0f + erff(v1 * 0.70710678118654752f));
                }
                if (accumulate) {
                    float* crow = &Cf[(long)rr * ldc + c];
                    crow[0] += v0; crow[1] += v1;
                } else {
                    *reinterpret_cast<unsigned*>(&Cb[(long)rr * ldc + c]) = packbf(v0, v1);
                }
            }
        }
    }
}

// ---------------- fused flash attention (bf16 mma, mma row-sum, exp2 softmax) ----------------
#define KVW 72
#define CEXP 0.18033688011112042f   // 0.125 * log2(e)
#define ONESBF 0x3F803F80u          // bf16x2 {1.0, 1.0}

__global__ __launch_bounds__(256, 2) void flash_bf(
    const __nv_bfloat16* __restrict__ Qg,
    const __nv_bfloat16* __restrict__ Kg,
    const __nv_bfloat16* __restrict__ Vg,
    __nv_bfloat16* __restrict__ Out,
    int causal)
{
    __shared__ __nv_bfloat16 Ks[2][64 * KVW];
    __shared__ __nv_bfloat16 Vs[2][64 * KVW];

    int bh = blockIdx.y;
    int b = bh >> 3, h = bh & 7;
    int q0 = blockIdx.x * 128;
    long base = (long)bh * T_ * HS_;
    const __nv_bfloat16* Qb = Qg + base;
    const __nv_bfloat16* Kb = Kg + base;
    const __nv_bfloat16* Vb = Vg + base;

    int tid = threadIdx.x;
    int lane = tid & 31, w = tid >> 5;
    int g = lane >> 2, t4 = lane & 3;
    int wr = w * 16;

    auto loadKV = [&](int st, int s0) {
        #pragma unroll
        for (int j = 0; j < 2; j++) {
            int c = tid + j * 256;
            int row = c >> 3;
            int cc = (c & 7) * 8;
            cp16(&Ks[st][row * KVW + cc], Kb + (long)(s0 + row) * HS_ + cc);
            cp16(&Vs[st][row * KVW + cc], Vb + (long)(s0 + row) * HS_ + cc);
        }
    };

    unsigned Qa[4][4];
    {
        const __nv_bfloat16* q0p = Qb + (long)(q0 + wr + g) * HS_;
        const __nv_bfloat16* q1p = q0p + 8 * HS_;
        #pragma unroll
        for (int c = 0; c < 4; c++) {
            Qa[c][0] = *reinterpret_cast<const unsigned*>(&q0p[c * 16 + 2 * t4]);
            Qa[c][1] = *reinterpret_cast<const unsigned*>(&q1p[c * 16 + 2 * t4]);
            Qa[c][2] = *reinterpret_cast<const unsigned*>(&q0p[c * 16 + 8 + 2 * t4]);
            Qa[c][3] = *reinterpret_cast<const unsigned*>(&q1p[c * 16 + 8 + 2 * t4]);
        }
    }

    float Oacc[8][4];
    #pragma unroll
    for (int i = 0; i < 8; i++)
        #pragma unroll
        for (int j = 0; j < 4; j++) Oacc[i][j] = 0.f;
    float Lacc[4] = {0.f, 0.f, 0.f, 0.f};   // row-sum accumulator (P·1 via mma)
    float m0 = -1e30f, m1 = -1e30f;         // m tracked in RAW S units

    int nT = causal ? (q0 / 64 + 2) : (T_ / 64);

    loadKV(0, 0);
    CP_COMMIT();

    int lmj = lane >> 3, lmt = lane & 7;
    int vt_off = ((lmj & 1) * 8 + lmt) * KVW + (lmj >> 1) * 8;          // V (trans)
    int kt_row = (lane & 7) + 8 * (lane >> 4);                          // K (non-trans)
    int kt_add = ((lane >> 3) & 1) * 8;

    for (int it = 0; it < nT; it++) {
        int s = it & 1;
        int s0 = it * 64;
        CP_WAIT(0);
        __syncthreads();
        if (it + 1 < nT) {
            loadKV(s ^ 1, (it + 1) * 64);
            CP_COMMIT();
        }

        unsigned kbase = sm_u32(&Ks[s][0]);
        unsigned vbase = sm_u32(&Vs[s][0]);

        // S = Q K^T (raw; scale folded into exp2)
        float S[8][4];
        #pragma unroll
        for (int nf = 0; nf < 8; nf++)
            #pragma unroll
            for (int j = 0; j < 4; j++) S[nf][j] = 0.f;

        #pragma unroll
        for (int c = 0; c < 4; c++) {
            #pragma unroll
            for (int nfp = 0; nfp < 4; nfp++) {
                unsigned r0, r1, r2, r3;
                unsigned addr = kbase + (unsigned)(((nfp * 16 + kt_row) * KVW + c * 16 + kt_add) * 2);
                asm volatile(
                    "ldmatrix.sync.aligned.m8n8.x4.shared.b16 {%0,%1,%2,%3}, [%4];"
                    : "=r"(r0), "=r"(r1), "=r"(r2), "=r"(r3) : "r"(addr));
                mma_bf16(S[2 * nfp],     Qa[c], r0, r1);
                mma_bf16(S[2 * nfp + 1], Qa[c], r2, r3);
            }
        }

        // causal mask (diagonal tiles only)
        if (causal && (s0 + 63 > q0 + wr)) {
            int r0g = q0 + wr + g;
            #pragma unroll
            for (int nf = 0; nf < 8; nf++) {
                int cbase = s0 + nf * 8 + 2 * t4;
                if (cbase     > r0g)     S[nf][0] = -1e30f;
                if (cbase + 1 > r0g)     S[nf][1] = -1e30f;
                if (cbase     > r0g + 8) S[nf][2] = -1e30f;
                if (cbase + 1 > r0g + 8) S[nf][3] = -1e30f;
            }
        }

        // row max (raw units), reduce over t4 quad
        float tm0 = -1e30f, tm1 = -1e30f;
        #pragma unroll
        for (int nf = 0; nf < 8; nf++) {
            tm0 = fmaxf(tm0, fmaxf(S[nf][0], S[nf][1]));
            tm1 = fmaxf(tm1, fmaxf(S[nf][2], S[nf][3]));
        }
        tm0 = fmaxf(tm0, __shfl_xor_sync(0xffffffffu, tm0, 1));
        tm0 = fmaxf(tm0, __shfl_xor_sync(0xffffffffu, tm0, 2));
        tm1 = fmaxf(tm1, __shfl_xor_sync(0xffffffffu, tm1, 1));
        tm1 = fmaxf(tm1, __shfl_xor_sync(0xffffffffu, tm1, 2));

        float nm0 = fmaxf(m0, tm0), nm1 = fmaxf(m1, tm1);
        float f0 = ex2f((m0 - nm0) * CEXP), f1 = ex2f((m1 - nm1) * CEXP);
        m0 = nm0; m1 = nm1;

        #pragma unroll
        for (int nf = 0; nf < 8; nf++) {
            S[nf][0] = ex2f((S[nf][0] - nm0) * CEXP);
            S[nf][1] = ex2f((S[nf][1] - nm0) * CEXP);
            S[nf][2] = ex2f((S[nf][2] - nm1) * CEXP);
            S[nf][3] = ex2f((S[nf][3] - nm1) * CEXP);
        }

        // rescale O and L accumulators
        #pragma unroll
        for (int nf = 0; nf < 8; nf++) {
            Oacc[nf][0] *= f0; Oacc[nf][1] *= f0;
            Oacc[nf][2] *= f1; Oacc[nf][3] *= f1;
        }
        Lacc[0] *= f0; Lacc[1] *= f0; Lacc[2] *= f1; Lacc[3] *= f1;

        // O += P V ; L += P·1  (row-sum as an extra n=8 mma with ones-B)
        #pragma unroll
        for (int c = 0; c < 4; c++) {
            unsigned a4[4];
            a4[0] = packbf(S[2 * c][0],     S[2 * c][1]);
            a4[1] = packbf(S[2 * c][2],     S[2 * c][3]);
            a4[2] = packbf(S[2 * c + 1][0], S[2 * c + 1][1]);
            a4[3] = packbf(S[2 * c + 1][2], S[2 * c + 1][3]);
            mma_bf16(Lacc, a4, ONESBF, ONESBF);
            #pragma unroll
            for (int gi = 0; gi < 4; gi++) {
                unsigned r0, r1, r2, r3;
                unsigned addr = vbase + (unsigned)((c * 16 * KVW + gi * 16 + vt_off) * 2);
                asm volatile(
                    "ldmatrix.sync.aligned.m8n8.x4.trans.shared.b16 {%0,%1,%2,%3}, [%4];"
                    : "=r"(r0), "=r"(r1), "=r"(r2), "=r"(r3) : "r"(addr));
                mma_bf16(Oacc[2 * gi],     a4, r0, r1);
                mma_bf16(Oacc[2 * gi + 1], a4, r2, r3);
            }
        }
    }

    // epilogue: normalize and write bf16 [B,T,C]
    float inv0 = 1.f / Lacc[0], inv1 = 1.f / Lacc[2];
    __nv_bfloat16* o0 = Out + ((long)b * T_ + q0 + wr + g) * C_ + h * HS_;
    __nv_bfloat16* o1 = Out + ((long)b * T_ + q0 + wr + g + 8) * C_ + h * HS_;
    #pragma unroll
    for (int nf = 0; nf < 8; nf++) {
        int c = nf * 8 + 2 * t4;
        *reinterpret_cast<unsigned*>(&o0[c]) = packbf(Oacc[nf][0] * inv0, Oacc[nf][1] * inv0);
        *reinterpret_cast<unsigned*>(&o1[c]) = packbf(Oacc[nf][2] * inv1, Oacc[nf][3] * inv1);
    }
}

// ---------------- orchestration ----------------
extern "C" void kernel_launch(void* const* d_in, const int* in_sizes, int n_in,
                              void* d_out, int out_size)
{
    const float* hidden = (const float*)d_in[0];
    const float* target = (const float*)d_in[1];
    const float* Wq_s = (const float*)d_in[2];
    const float* Wk_s = (const float*)d_in[3];
    const float* Wv_s = (const float*)d_in[4];
    const float* Wo_s = (const float*)d_in[5];
    const float* bo_s = (const float*)d_in[6];
    const float* Wq_x = (const float*)d_in[7];
    const float* Wk_x = (const float*)d_in[8];
    const float* Wv_x = (const float*)d_in[9];
    const float* Wo_x = (const float*)d_in[10];
    const float* bo_x = (const float*)d_in[11];
    const float* W1 = (const float*)d_in[12];
    const float* b1 = (const float*)d_in[13];
    const float* W2 = (const float*)d_in[14];
    const float* b2 = (const float*)d_in[15];
    const float* g1 = (const float*)d_in[16];
    const float* g2 = (const float*)d_in[17];
    const float* g3 = (const float*)d_in[18];
    const float* g4 = (const float*)d_in[19];

    float* t = (float*)d_out;

    __nv_bfloat16 *xnb, *hnb, *qb, *kb, *vb, *attnb, *ffb;
    cudaGetSymbolAddress((void**)&xnb, g_xnb);
    cudaGetSymbolAddress((void**)&hnb, g_hnb);
    cudaGetSymbolAddress((void**)&qb, g_q);
    cudaGetSymbolAddress((void**)&kb, g_k);
    cudaGetSymbolAddress((void**)&vb, g_v);
    cudaGetSymbolAddress((void**)&attnb, g_attnb);
    cudaGetSymbolAddress((void**)&ffb, g_ffb);

    copy_k<<<(BTC_ / 4 + 255) / 256, 256>>>((float4*)t, (const float4*)target, BTC_ / 4);

    const long HCHS = (long)H_ * C_ * HS_;   // per-layer weight stride

    dim3 gQKV(12, T_ / 128, NB);             // 384 CTAs (MI=4)
    dim3 gQx(4, T_ / 64, NB);                // 256 CTAs (MI=2)
    dim3 gKVx(8, T_ / 128, NB);              // 256 CTAs (MI=4)
    dim3 gO(C_ / 128, BT_ / 64, 1);          // 256 CTAs (MI=2)
    dim3 gF1(FF_ / 128, BT_ / 128, 1);       // 256 CTAs (MI=4)
    dim3 gF2(C_ / 128, BT_ / 64, 1);         // 256 CTAs (MI=2)
    dim3 gFl(T_ / 128, BH_, 1);

    for (int l = 0; l < NL; l++) {
        // ======== masked self-attention ========
        rmsnorm_k<<<BT_, 256>>>(t, g1 + (long)l * C_, xnb);

        gemm_qkv_bf<4><<<gQKV, 256>>>(xnb,
            Wq_s + l * HCHS, Wk_s + l * HCHS, Wv_s + l * HCHS,
            qb, kb, vb, 4);

        flash_bf<<<gFl, 256>>>(qb, kb, vb, attnb, 1);

        gemm_bf<2><<<gO, 256>>>(C_,
            attnb, C_,
            Wo_s + (long)l * C_ * C_, C_,
            bo_s + (long)l * C_,
            t, nullptr, C_, 1, 0);

        // ======== cross-attention ========
        rmsnorm_k<<<BT_, 256>>>(hidden, g2 + (long)l * C_, hnb);
        rmsnorm_k<<<BT_, 256>>>(t, g3 + (long)l * C_, xnb);

        gemm_qkv_bf<2><<<gQx, 256>>>(xnb,
            Wq_x + l * HCHS, Wq_x + l * HCHS, Wq_x + l * HCHS,
            qb, qb, qb, 4);
        gemm_qkv_bf<4><<<gKVx, 256>>>(hnb,
            Wk_x + l * HCHS, Wv_x + l * HCHS, Wv_x + l * HCHS,
            kb, vb, vb, 4);

        flash_bf<<<gFl, 256>>>(qb, kb, vb, attnb, 0);

        gemm_bf<2><<<gO, 256>>>(C_,
            attnb, C_,
            Wo_x + (long)l * C_ * C_, C_,
            bo_x + (long)l * C_,
            t, nullptr, C_, 1, 0);

        // ======== GELU FFN ========
        rmsnorm_k<<<BT_, 256>>>(t, g4 + (long)l * C_, xnb);

        gemm_bf<4><<<gF1, 256>>>(C_,
            xnb, C_,
            W1 + (long)l * C_ * FF_, FF_,
            b1 + (long)l * FF_,
            nullptr, ffb, FF_, 0, 1);

        gemm_bf<2><<<gF2, 256>>>(FF_,
            ffb, FF_,
            W2 + (long)l * FF_ * C_, C_,
            b2 + (long)l * C_,
            t, nullptr, C_, 1, 0);
    }
}

// round 12
// speedup vs baseline: 1.5988x; 1.5988x over previous
#include <cuda_runtime.h>
#include <cuda_bf16.h>
#include <math.h>

// Problem dims
#define NL  2
#define NB  2
#define T_  2048
#define C_  512
#define H_  8
#define FF_ 1024
#define HS_ 64
#define EPS_ 1.1920929e-07f

#define BT_  (NB * T_)        // 4096 rows
#define BTC_ (NB * T_ * C_)   // 2097152
#define BH_  (NB * H_)        // 16

// ---------------- scratch ----------------
__device__ __nv_bfloat16 g_xnb[BTC_];    // bf16 normed activations
__device__ __nv_bfloat16 g_hnb[BTC_];
__device__ __nv_bfloat16 g_q[BTC_];      // [B,H,T,HS] bf16
__device__ __nv_bfloat16 g_k[BTC_];
__device__ __nv_bfloat16 g_v[BTC_];
__device__ __nv_bfloat16 g_attnb[BTC_];  // [B,T,C] bf16 (flash out)
__device__ __nv_bfloat16 g_ffb[NB * T_ * FF_];

// ---------------- cp.async helpers ----------------
__device__ __forceinline__ unsigned sm_u32(const void* p) {
    return (unsigned)__cvta_generic_to_shared(p);
}
__device__ __forceinline__ void cp16(void* dst_smem, const void* src) {
    asm volatile("cp.async.cg.shared.global [%0], [%1], 16;"
                 :: "r"(sm_u32(dst_smem)), "l"(src));
}
#define CP_COMMIT() asm volatile("cp.async.commit_group;")
#define CP_WAIT(n)  asm volatile("cp.async.wait_group %0;" :: "n"(n))

// ---------------- helpers ----------------
// rmsnorm -> bf16 output
__global__ __launch_bounds__(256) void rmsnorm_k(
    const float* __restrict__ x, const float* __restrict__ g,
    __nv_bfloat16* __restrict__ outb)
{
    long row = blockIdx.x;
    const float* xr = x + row * C_;
    int tid = threadIdx.x;
    float v0 = xr[tid];
    float v1 = xr[tid + 256];
    float ss = v0 * v0 + v1 * v1;

    __shared__ float red[8];
    #pragma unroll
    for (int o = 16; o; o >>= 1) ss += __shfl_xor_sync(0xffffffffu, ss, o);
    if ((tid & 31) == 0) red[tid >> 5] = ss;
    __syncthreads();
    if (tid == 0) {
        float s = 0.f;
        #pragma unroll
        for (int w = 0; w < 8; w++) s += red[w];
        red[0] = rsqrtf(s * (1.0f / C_) + EPS_);
    }
    __syncthreads();
    float r = red[0];
    __nv_bfloat16* ob = outb + row * C_;
    ob[tid]       = __float2bfloat16_rn(v0 * r * g[tid]);
    ob[tid + 256] = __float2bfloat16_rn(v1 * r * g[tid + 256]);
}

// ---------------- mma helpers ----------------
__device__ __forceinline__ void mma_bf16(float* d, const unsigned* a, unsigned b0, unsigned b1) {
    asm volatile(
        "mma.sync.aligned.m16n8k16.row.col.f32.bf16.bf16.f32 "
        "{%0,%1,%2,%3}, {%4,%5,%6,%7}, {%8,%9}, {%0,%1,%2,%3};"
        : "+f"(d[0]), "+f"(d[1]), "+f"(d[2]), "+f"(d[3])
        : "r"(a[0]), "r"(a[1]), "r"(a[2]), "r"(a[3]), "r"(b0), "r"(b1));
}
__device__ __forceinline__ unsigned packbf(float lo, float hi) {
    unsigned d;
    asm("cvt.rn.bf16x2.f32 %0, %1, %2;" : "=r"(d) : "f"(hi), "f"(lo));
    return d;
}
__device__ __forceinline__ float ex2f(float x) {
    float y;
    asm("ex2.approx.f32 %0, %1;" : "=f"(y) : "f"(x));
    return y;
}

#define QASTR 40    // A smem row pitch (bf16): 32 + 8 pad
#define QBSTR 136   // B smem row pitch (bf16): 128 + 8 pad

// ---------------- bf16 QKV projection GEMM (head-blocked B and C) ----------------
// Per-sel A pointers: sel picks (A, B, C) triple. 128x128 tile, BK=32.
__global__ __launch_bounds__(256) void gemm_qkv_bf(
    const __nv_bfloat16* __restrict__ A0, const __nv_bfloat16* __restrict__ A1,
    const __nv_bfloat16* __restrict__ A2,
    const float* __restrict__ B0, const float* __restrict__ B1, const float* __restrict__ B2,
    __nv_bfloat16* __restrict__ C0, __nv_bfloat16* __restrict__ C1, __nv_bfloat16* __restrict__ C2,
    int nColBlk)
{
    __shared__ __nv_bfloat16 As[2][128 * QASTR];
    __shared__ __nv_bfloat16 Bs[2][32 * QBSTR];

    int sel  = blockIdx.x / nColBlk;
    int colb = blockIdx.x - sel * nColBlk;
    const __nv_bfloat16* A = (sel == 0) ? A0 : (sel == 1) ? A1 : A2;
    const float* B = (sel == 0) ? B0 : (sel == 1) ? B1 : B2;
    __nv_bfloat16* Cp = ((sel == 0) ? C0 : (sel == 1) ? C1 : C2)
                        + (long)blockIdx.z * H_ * T_ * HS_;

    const __nv_bfloat16* Ab = A + (long)blockIdx.z * T_ * C_ + (long)(blockIdx.y * 128) * C_;
    int col0 = colb * 128;

    int tid = threadIdx.x, lane = tid & 31, w = tid >> 5;
    int g = lane >> 2, t4 = lane & 3;
    int wm = w & 1, wn = w >> 1;

    float acc[4][4][4];
    #pragma unroll
    for (int i = 0; i < 4; i++)
        #pragma unroll
        for (int j = 0; j < 4; j++)
            #pragma unroll
            for (int q = 0; q < 4; q++) acc[i][j][q] = 0.f;

    auto cpA = [&](int st, int k0) {
        #pragma unroll
        for (int j = 0; j < 2; j++) {
            int c = tid * 2 + j;
            int row = c >> 2, kc = (c & 3) * 8;
            cp16(&As[st][row * QASTR + kc], Ab + (long)row * C_ + k0 + kc);
        }
    };

    int bk = tid >> 3;
    int bn0 = (tid & 7) * 16;
    float4 bp[4];
    auto ldB = [&](int k0) {
        #pragma unroll
        for (int jj = 0; jj < 4; jj++) {
            int gc = col0 + bn0 + jj * 4;
            bp[jj] = *reinterpret_cast<const float4*>(
                &B[(long)(gc >> 6) * C_ * HS_ + (long)(k0 + bk) * HS_ + (gc & 63)]);
        }
    };
    auto stB = [&](int st) {
        #pragma unroll
        for (int jj = 0; jj < 4; jj++) {
            uint2 u = { packbf(bp[jj].x, bp[jj].y), packbf(bp[jj].z, bp[jj].w) };
            *reinterpret_cast<uint2*>(&Bs[st][bk * QBSTR + bn0 + jj * 4]) = u;
        }
    };

    int a_lrow = lane & 15, a_lk = (lane >> 4) * 8;
    int b_lrow = ((lane >> 3) & 1) * 8 + (lane & 7), b_lc = (lane >> 4) * 8;

    cpA(0, 0); CP_COMMIT();
    ldB(0);

    #pragma unroll 1
    for (int kt = 0; kt < C_ / 32; kt++) {
        int s = kt & 1;
        CP_WAIT(0);
        stB(s);
        __syncthreads();
        if (kt + 1 < C_ / 32) {
            cpA(s ^ 1, (kt + 1) * 32);
            CP_COMMIT();
            ldB((kt + 1) * 32);
        }

        #pragma unroll
        for (int kc = 0; kc < 32; kc += 16) {
            unsigned afr[4][4];
            #pragma unroll
            for (int mi = 0; mi < 4; mi++) {
                int m0 = wm * 64 + mi * 16;
                unsigned addr = sm_u32(&As[s][(m0 + a_lrow) * QASTR + kc + a_lk]);
                asm volatile(
                    "ldmatrix.sync.aligned.m8n8.x4.shared.b16 {%0,%1,%2,%3}, [%4];"
                    : "=r"(afr[mi][0]), "=r"(afr[mi][1]), "=r"(afr[mi][2]), "=r"(afr[mi][3])
                    : "r"(addr));
            }
            #pragma unroll
            for (int gi = 0; gi < 2; gi++) {
                int n0 = wn * 32 + gi * 16;
                unsigned r0, r1, r2, r3;
                unsigned addr = sm_u32(&Bs[s][(kc + b_lrow) * QBSTR + n0 + b_lc]);
                asm volatile(
                    "ldmatrix.sync.aligned.m8n8.x4.trans.shared.b16 {%0,%1,%2,%3}, [%4];"
                    : "=r"(r0), "=r"(r1), "=r"(r2), "=r"(r3) : "r"(addr));
                #pragma unroll
                for (int mi = 0; mi < 4; mi++) {
                    mma_bf16(acc[mi][2 * gi],     afr[mi], r0, r1);
                    mma_bf16(acc[mi][2 * gi + 1], afr[mi], r2, r3);
                }
            }
        }
    }

    int row0 = blockIdx.y * 128;
    #pragma unroll
    for (int mi = 0; mi < 4; mi++) {
        #pragma unroll
        for (int ni = 0; ni < 4; ni++) {
            int r0 = row0 + wm * 64 + mi * 16 + g;
            int c  = col0 + wn * 32 + ni * 8 + t4 * 2;
            long hb = (long)(c >> 6) * T_ * HS_ + (c & 63);
            #pragma unroll
            for (int half = 0; half < 2; half++) {
                int rr = r0 + half * 8;
                *reinterpret_cast<unsigned*>(&Cp[hb + (long)rr * HS_]) =
                    packbf(acc[mi][ni][half * 2 + 0], acc[mi][ni][half * 2 + 1]);
            }
        }
    }
}

// ---------------- bf16 dense GEMM (plain layouts): O-proj / FFN ----------------
// resid != null: Cf = resid + v (fresh residual base). else accumulate: Cf += v.
// else: Cb = bf16(v) (with optional gelu).
__global__ __launch_bounds__(256) void gemm_bf(
    int K,
    const __nv_bfloat16* __restrict__ A, int lda,
    const float* __restrict__ B, int ldb,
    const float* __restrict__ bias,
    float* __restrict__ Cf, __nv_bfloat16* __restrict__ Cb,
    const float* __restrict__ resid,
    int ldc, int accumulate, int gelu_act)
{
    __shared__ __nv_bfloat16 As[2][128 * QASTR];
    __shared__ __nv_bfloat16 Bs[2][32 * QBSTR];

    int row0 = blockIdx.y * 128;
    int col0 = blockIdx.x * 128;

    int tid = threadIdx.x, lane = tid & 31, w = tid >> 5;
    int g = lane >> 2, t4 = lane & 3;
    int wm = w & 1, wn = w >> 1;

    float acc[4][4][4];
    #pragma unroll
    for (int i = 0; i < 4; i++)
        #pragma unroll
        for (int j = 0; j < 4; j++)
            #pragma unroll
            for (int q = 0; q < 4; q++) acc[i][j][q] = 0.f;

    const __nv_bfloat16* Ab = A + (long)row0 * lda;

    auto cpA = [&](int st, int k0) {
        #pragma unroll
        for (int j = 0; j < 2; j++) {
            int c = tid * 2 + j;
            int row = c >> 2, kc = (c & 3) * 8;
            cp16(&As[st][row * QASTR + kc], Ab + (long)row * lda + k0 + kc);
        }
    };

    int bk = tid >> 3;
    int bn0 = (tid & 7) * 16;
    float4 bp[4];
    auto ldB = [&](int k0) {
        #pragma unroll
        for (int jj = 0; jj < 4; jj++)
            bp[jj] = *reinterpret_cast<const float4*>(
                &B[(long)(k0 + bk) * ldb + col0 + bn0 + jj * 4]);
    };
    auto stB = [&](int st) {
        #pragma unroll
        for (int jj = 0; jj < 4; jj++) {
            uint2 u = { packbf(bp[jj].x, bp[jj].y), packbf(bp[jj].z, bp[jj].w) };
            *reinterpret_cast<uint2*>(&Bs[st][bk * QBSTR + bn0 + jj * 4]) = u;
        }
    };

    int a_lrow = lane & 15, a_lk = (lane >> 4) * 8;
    int b_lrow = ((lane >> 3) & 1) * 8 + (lane & 7), b_lc = (lane >> 4) * 8;

    cpA(0, 0); CP_COMMIT();
    ldB(0);

    int nK = K / 32;
    #pragma unroll 1
    for (int kt = 0; kt < nK; kt++) {
        int s = kt & 1;
        CP_WAIT(0);
        stB(s);
        __syncthreads();
        if (kt + 1 < nK) {
            cpA(s ^ 1, (kt + 1) * 32);
            CP_COMMIT();
            ldB((kt + 1) * 32);
        }

        #pragma unroll
        for (int kc = 0; kc < 32; kc += 16) {
            unsigned afr[4][4];
            #pragma unroll
            for (int mi = 0; mi < 4; mi++) {
                int m0 = wm * 64 + mi * 16;
                unsigned addr = sm_u32(&As[s][(m0 + a_lrow) * QASTR + kc + a_lk]);
                asm volatile(
                    "ldmatrix.sync.aligned.m8n8.x4.shared.b16 {%0,%1,%2,%3}, [%4];"
                    : "=r"(afr[mi][0]), "=r"(afr[mi][1]), "=r"(afr[mi][2]), "=r"(afr[mi][3])
                    : "r"(addr));
            }
            #pragma unroll
            for (int gi = 0; gi < 2; gi++) {
                int n0 = wn * 32 + gi * 16;
                unsigned r0, r1, r2, r3;
                unsigned addr = sm_u32(&Bs[s][(kc + b_lrow) * QBSTR + n0 + b_lc]);
                asm volatile(
                    "ldmatrix.sync.aligned.m8n8.x4.trans.shared.b16 {%0,%1,%2,%3}, [%4];"
                    : "=r"(r0), "=r"(r1), "=r"(r2), "=r"(r3) : "r"(addr));
                #pragma unroll
                for (int mi = 0; mi < 4; mi++) {
                    mma_bf16(acc[mi][2 * gi],     afr[mi], r0, r1);
                    mma_bf16(acc[mi][2 * gi + 1], afr[mi], r2, r3);
                }
            }
        }
    }

    #pragma unroll
    for (int mi = 0; mi < 4; mi++) {
        #pragma unroll
        for (int ni = 0; ni < 4; ni++) {
            int r0 = row0 + wm * 64 + mi * 16 + g;
            int c  = col0 + wn * 32 + ni * 8 + t4 * 2;
            #pragma unroll
            for (int half = 0; half < 2; half++) {
                int rr = r0 + half * 8;
                float v0 = acc[mi][ni][half * 2 + 0];
                float v1 = acc[mi][ni][half * 2 + 1];
                if (bias) { v0 += bias[c]; v1 += bias[c + 1]; }
                if (gelu_act) {
                    v0 = 0.5f * v0 * (1.0f + erff(v0 * 0.70710678118654752f));
                    v1 = 0.5f * v1 * (1.0f + erff(v1 * 0.70710678118654752f));
                }
                if (resid) {
                    const float* rrow = &resid[(long)rr * ldc + c];
                    float* crow = &Cf[(long)rr * ldc + c];
                    crow[0] = rrow[0] + v0; crow[1] = rrow[1] + v1;
                } else if (accumulate) {
                    float* crow = &Cf[(long)rr * ldc + c];
                    crow[0] += v0; crow[1] += v1;
                } else {
                    *reinterpret_cast<unsigned*>(&Cb[(long)rr * ldc + c]) = packbf(v0, v1);
                }
            }
        }
    }
}

// ---------------- fused flash attention (bf16 mma, ldmatrix frags, exp2 softmax) ----------------
// (R9 version — known good; do not perturb.)
#define KVW 72
#define CEXP 0.18033688011112042f   // 0.125 * log2(e)

__global__ __launch_bounds__(256, 2) void flash_bf(
    const __nv_bfloat16* __restrict__ Qg,
    const __nv_bfloat16* __restrict__ Kg,
    const __nv_bfloat16* __restrict__ Vg,
    __nv_bfloat16* __restrict__ Out,
    int causal)
{
    __shared__ __nv_bfloat16 Ks[2][64 * KVW];
    __shared__ __nv_bfloat16 Vs[2][64 * KVW];

    int bh = blockIdx.y;
    int b = bh >> 3, h = bh & 7;
    int q0 = blockIdx.x * 128;
    long base = (long)bh * T_ * HS_;
    const __nv_bfloat16* Qb = Qg + base;
    const __nv_bfloat16* Kb = Kg + base;
    const __nv_bfloat16* Vb = Vg + base;

    int tid = threadIdx.x;
    int lane = tid & 31, w = tid >> 5;
    int g = lane >> 2, t4 = lane & 3;
    int wr = w * 16;

    auto loadKV = [&](int st, int s0) {
        #pragma unroll
        for (int j = 0; j < 2; j++) {
            int c = tid + j * 256;
            int row = c >> 3;
            int cc = (c & 7) * 8;
            cp16(&Ks[st][row * KVW + cc], Kb + (long)(s0 + row) * HS_ + cc);
            cp16(&Vs[st][row * KVW + cc], Vb + (long)(s0 + row) * HS_ + cc);
        }
    };

    unsigned Qa[4][4];
    {
        const __nv_bfloat16* q0p = Qb + (long)(q0 + wr + g) * HS_;
        const __nv_bfloat16* q1p = q0p + 8 * HS_;
        #pragma unroll
        for (int c = 0; c < 4; c++) {
            Qa[c][0] = *reinterpret_cast<const unsigned*>(&q0p[c * 16 + 2 * t4]);
            Qa[c][1] = *reinterpret_cast<const unsigned*>(&q1p[c * 16 + 2 * t4]);
            Qa[c][2] = *reinterpret_cast<const unsigned*>(&q0p[c * 16 + 8 + 2 * t4]);
            Qa[c][3] = *reinterpret_cast<const unsigned*>(&q1p[c * 16 + 8 + 2 * t4]);
        }
    }

    float Oacc[8][4];
    #pragma unroll
    for (int i = 0; i < 8; i++)
        #pragma unroll
        for (int j = 0; j < 4; j++) Oacc[i][j] = 0.f;
    // m tracked in RAW S units (pre-0.125 scale)
    float m0 = -1e30f, m1 = -1e30f, l0 = 0.f, l1 = 0.f;

    int nT = causal ? (q0 / 64 + 2) : (T_ / 64);

    loadKV(0, 0);
    CP_COMMIT();

    // ldmatrix per-thread offsets
    int lmj = lane >> 3, lmt = lane & 7;
    int vt_off = ((lmj & 1) * 8 + lmt) * KVW + (lmj >> 1) * 8;          // V (trans)
    int kt_row = (lane & 7) + 8 * (lane >> 4);                          // K (non-trans)
    int kt_add = ((lane >> 3) & 1) * 8;

    for (int it = 0; it < nT; it++) {
        int s = it & 1;
        int s0 = it * 64;
        CP_WAIT(0);
        __syncthreads();
        if (it + 1 < nT) {
            loadKV(s ^ 1, (it + 1) * 64);
            CP_COMMIT();
        }

        unsigned kbase = sm_u32(&Ks[s][0]);
        unsigned vbase = sm_u32(&Vs[s][0]);

        // S = Q K^T (raw; scale folded into exp2)
        float S[8][4];
        #pragma unroll
        for (int nf = 0; nf < 8; nf++)
            #pragma unroll
            for (int j = 0; j < 4; j++) S[nf][j] = 0.f;

        #pragma unroll
        for (int c = 0; c < 4; c++) {
            #pragma unroll
            for (int nfp = 0; nfp < 4; nfp++) {
                unsigned r0, r1, r2, r3;
                unsigned addr = kbase + (unsigned)(((nfp * 16 + kt_row) * KVW + c * 16 + kt_add) * 2);
                asm volatile(
                    "ldmatrix.sync.aligned.m8n8.x4.shared.b16 {%0,%1,%2,%3}, [%4];"
                    : "=r"(r0), "=r"(r1), "=r"(r2), "=r"(r3) : "r"(addr));
                mma_bf16(S[2 * nfp],     Qa[c], r0, r1);
                mma_bf16(S[2 * nfp + 1], Qa[c], r2, r3);
            }
        }

        // causal mask (diagonal tiles only)
        if (causal && (s0 + 63 > q0 + wr)) {
            int r0g = q0 + wr + g;
            #pragma unroll
            for (int nf = 0; nf < 8; nf++) {
                int cbase = s0 + nf * 8 + 2 * t4;
                if (cbase     > r0g)     S[nf][0] = -1e30f;
                if (cbase + 1 > r0g)     S[nf][1] = -1e30f;
                if (cbase     > r0g + 8) S[nf][2] = -1e30f;
                if (cbase + 1 > r0g + 8) S[nf][3] = -1e30f;
            }
        }

        // row max (raw units), reduce over t4 quad
        float tm0 = -1e30f, tm1 = -1e30f;
        #pragma unroll
        for (int nf = 0; nf < 8; nf++) {
            tm0 = fmaxf(tm0, fmaxf(S[nf][0], S[nf][1]));
            tm1 = fmaxf(tm1, fmaxf(S[nf][2], S[nf][3]));
        }
        tm0 = fmaxf(tm0, __shfl_xor_sync(0xffffffffu, tm0, 1));
        tm0 = fmaxf(tm0, __shfl_xor_sync(0xffffffffu, tm0, 2));
        tm1 = fmaxf(tm1, __shfl_xor_sync(0xffffffffu, tm1, 1));
        tm1 = fmaxf(tm1, __shfl_xor_sync(0xffffffffu, tm1, 2));

        float nm0 = fmaxf(m0, tm0), nm1 = fmaxf(m1, tm1);
        float f0 = ex2f((m0 - nm0) * CEXP), f1 = ex2f((m1 - nm1) * CEXP);

        float rs0 = 0.f, rs1 = 0.f;
        #pragma unroll
        for (int nf = 0; nf < 8; nf++) {
            S[nf][0] = ex2f((S[nf][0] - nm0) * CEXP);
            S[nf][1] = ex2f((S[nf][1] - nm0) * CEXP);
            S[nf][2] = ex2f((S[nf][2] - nm1) * CEXP);
            S[nf][3] = ex2f((S[nf][3] - nm1) * CEXP);
            rs0 += S[nf][0] + S[nf][1];
            rs1 += S[nf][2] + S[nf][3];
        }
        rs0 += __shfl_xor_sync(0xffffffffu, rs0, 1);
        rs0 += __shfl_xor_sync(0xffffffffu, rs0, 2);
        rs1 += __shfl_xor_sync(0xffffffffu, rs1, 1);
        rs1 += __shfl_xor_sync(0xffffffffu, rs1, 2);

        l0 = l0 * f0 + rs0;
        l1 = l1 * f1 + rs1;
        m0 = nm0; m1 = nm1;

        #pragma unroll
        for (int nf = 0; nf < 8; nf++) {
            Oacc[nf][0] *= f0; Oacc[nf][1] *= f0;
            Oacc[nf][2] *= f1; Oacc[nf][3] *= f1;
        }

        // O += P V : A-frags packed from S; B-frags via ldmatrix.trans
        #pragma unroll
        for (int c = 0; c < 4; c++) {
            unsigned a4[4];
            a4[0] = packbf(S[2 * c][0],     S[2 * c][1]);
            a4[1] = packbf(S[2 * c][2],     S[2 * c][3]);
            a4[2] = packbf(S[2 * c + 1][0], S[2 * c + 1][1]);
            a4[3] = packbf(S[2 * c + 1][2], S[2 * c + 1][3]);
            #pragma unroll
            for (int gi = 0; gi < 4; gi++) {
                unsigned r0, r1, r2, r3;
                unsigned addr = vbase + (unsigned)((c * 16 * KVW + gi * 16 + vt_off) * 2);
                asm volatile(
                    "ldmatrix.sync.aligned.m8n8.x4.trans.shared.b16 {%0,%1,%2,%3}, [%4];"
                    : "=r"(r0), "=r"(r1), "=r"(r2), "=r"(r3) : "r"(addr));
                mma_bf16(Oacc[2 * gi],     a4, r0, r1);
                mma_bf16(Oacc[2 * gi + 1], a4, r2, r3);
            }
        }
    }

    // epilogue: normalize and write bf16 [B,T,C]
    float inv0 = 1.f / l0, inv1 = 1.f / l1;
    __nv_bfloat16* o0 = Out + ((long)b * T_ + q0 + wr + g) * C_ + h * HS_;
    __nv_bfloat16* o1 = Out + ((long)b * T_ + q0 + wr + g + 8) * C_ + h * HS_;
    #pragma unroll
    for (int nf = 0; nf < 8; nf++) {
        int c = nf * 8 + 2 * t4;
        *reinterpret_cast<unsigned*>(&o0[c]) = packbf(Oacc[nf][0] * inv0, Oacc[nf][1] * inv0);
        *reinterpret_cast<unsigned*>(&o1[c]) = packbf(Oacc[nf][2] * inv1, Oacc[nf][3] * inv1);
    }
}

// ---------------- orchestration ----------------
extern "C" void kernel_launch(void* const* d_in, const int* in_sizes, int n_in,
                              void* d_out, int out_size)
{
    const float* hidden = (const float*)d_in[0];
    const float* target = (const float*)d_in[1];
    const float* Wq_s = (const float*)d_in[2];
    const float* Wk_s = (const float*)d_in[3];
    const float* Wv_s = (const float*)d_in[4];
    const float* Wo_s = (const float*)d_in[5];
    const float* bo_s = (const float*)d_in[6];
    const float* Wq_x = (const float*)d_in[7];
    const float* Wk_x = (const float*)d_in[8];
    const float* Wv_x = (const float*)d_in[9];
    const float* Wo_x = (const float*)d_in[10];
    const float* bo_x = (const float*)d_in[11];
    const float* W1 = (const float*)d_in[12];
    const float* b1 = (const float*)d_in[13];
    const float* W2 = (const float*)d_in[14];
    const float* b2 = (const float*)d_in[15];
    const float* g1 = (const float*)d_in[16];
    const float* g2 = (const float*)d_in[17];
    const float* g3 = (const float*)d_in[18];
    const float* g4 = (const float*)d_in[19];

    float* t = (float*)d_out;

    __nv_bfloat16 *xnb, *hnb, *qb, *kb, *vb, *attnb, *ffb;
    cudaGetSymbolAddress((void**)&xnb, g_xnb);
    cudaGetSymbolAddress((void**)&hnb, g_hnb);
    cudaGetSymbolAddress((void**)&qb, g_q);
    cudaGetSymbolAddress((void**)&kb, g_k);
    cudaGetSymbolAddress((void**)&vb, g_v);
    cudaGetSymbolAddress((void**)&attnb, g_attnb);
    cudaGetSymbolAddress((void**)&ffb, g_ffb);

    const long HCHS = (long)H_ * C_ * HS_;   // per-layer weight stride

    dim3 gQKV(12, T_ / 128, NB);             // 3 sels x 4 col-blocks, z=b
    dim3 gO(C_ / 128, BT_ / 128, 1);
    dim3 gF1(FF_ / 128, BT_ / 128, 1);
    dim3 gF2(C_ / 128, BT_ / 128, 1);
    dim3 gFl(T_ / 128, BH_, 1);

    for (int l = 0; l < NL; l++) {
        // ======== masked self-attention ========
        // layer 0: residual stream is still `target` (t not yet written)
        const float* tcur = (l == 0) ? target : t;
        rmsnorm_k<<<BT_, 256>>>(tcur, g1 + (long)l * C_, xnb);

        gemm_qkv_bf<<<gQKV, 256>>>(xnb, xnb, xnb,
            Wq_s + l * HCHS, Wk_s + l * HCHS, Wv_s + l * HCHS,
            qb, kb, vb, 4);

        flash_bf<<<gFl, 256>>>(qb, kb, vb, attnb, 1);

        gemm_bf<<<gO, 256>>>(C_,
            attnb, C_,
            Wo_s + (long)l * C_ * C_, C_,
            bo_s + (long)l * C_,
            t, nullptr, (l == 0) ? target : nullptr,
            C_, (l == 0) ? 0 : 1, 0);

        // ======== cross-attention (Q + K/V fused into one launch) ========
        rmsnorm_k<<<BT_, 256>>>(hidden, g2 + (long)l * C_, hnb);
        rmsnorm_k<<<BT_, 256>>>(t, g3 + (long)l * C_, xnb);

        gemm_qkv_bf<<<gQKV, 256>>>(xnb, hnb, hnb,
            Wq_x + l * HCHS, Wk_x + l * HCHS, Wv_x + l * HCHS,
            qb, kb, vb, 4);

        flash_bf<<<gFl, 256>>>(qb, kb, vb, attnb, 0);

        gemm_bf<<<gO, 256>>>(C_,
            attnb, C_,
            Wo_x + (long)l * C_ * C_, C_,
            bo_x + (long)l * C_,
            t, nullptr, nullptr,
            C_, 1, 0);

        // ======== GELU FFN ========
        rmsnorm_k<<<BT_, 256>>>(t, g4 + (long)l * C_, xnb);

        gemm_bf<<<gF1, 256>>>(C_,
            xnb, C_,
            W1 + (long)l * C_ * FF_, FF_,
            b1 + (long)l * FF_,
            nullptr, ffb, nullptr,
            FF_, 0, 1);

        gemm_bf<<<gF2, 256>>>(FF_,
            ffb, FF_,
            W2 + (long)l * FF_ * C_, C_,
            b2 + (long)l * C_,
            t, nullptr, nullptr,
            C_, 1, 0);
    }
}

// round 13
// speedup vs baseline: 1.6455x; 1.0291x over previous
#include <cuda_runtime.h>
#include <cuda_bf16.h>
#include <math.h>

// Problem dims
#define NL  2
#define NB  2
#define T_  2048
#define C_  512
#define H_  8
#define FF_ 1024
#define HS_ 64
#define EPS_ 1.1920929e-07f

#define BT_  (NB * T_)        // 4096 rows
#define BTC_ (NB * T_ * C_)   // 2097152
#define BH_  (NB * H_)        // 16

// ---------------- scratch ----------------
__device__ __nv_bfloat16 g_xnb[BTC_];    // bf16 normed activations
__device__ __nv_bfloat16 g_hnb[BTC_];
__device__ __nv_bfloat16 g_q[BTC_];      // [B,H,T,HS] bf16
__device__ __nv_bfloat16 g_k[BTC_];
__device__ __nv_bfloat16 g_v[BTC_];
__device__ __nv_bfloat16 g_attnb[BTC_];  // [B,T,C] bf16 (flash out)
__device__ __nv_bfloat16 g_ffb[NB * T_ * FF_];

// ---------------- cp.async helpers ----------------
__device__ __forceinline__ unsigned sm_u32(const void* p) {
    return (unsigned)__cvta_generic_to_shared(p);
}
__device__ __forceinline__ void cp16(void* dst_smem, const void* src) {
    asm volatile("cp.async.cg.shared.global [%0], [%1], 16;"
                 :: "r"(sm_u32(dst_smem)), "l"(src));
}
#define CP_COMMIT() asm volatile("cp.async.commit_group;")
#define CP_WAIT(n)  asm volatile("cp.async.wait_group %0;" :: "n"(n))

// ---------------- helpers ----------------
// rmsnorm -> bf16 output
__global__ __launch_bounds__(256) void rmsnorm_k(
    const float* __restrict__ x, const float* __restrict__ g,
    __nv_bfloat16* __restrict__ outb)
{
    long row = blockIdx.x;
    const float* xr = x + row * C_;
    int tid = threadIdx.x;
    float v0 = xr[tid];
    float v1 = xr[tid + 256];
    float ss = v0 * v0 + v1 * v1;

    __shared__ float red[8];
    #pragma unroll
    for (int o = 16; o; o >>= 1) ss += __shfl_xor_sync(0xffffffffu, ss, o);
    if ((tid & 31) == 0) red[tid >> 5] = ss;
    __syncthreads();
    if (tid == 0) {
        float s = 0.f;
        #pragma unroll
        for (int w = 0; w < 8; w++) s += red[w];
        red[0] = rsqrtf(s * (1.0f / C_) + EPS_);
    }
    __syncthreads();
    float r = red[0];
    __nv_bfloat16* ob = outb + row * C_;
    ob[tid]       = __float2bfloat16_rn(v0 * r * g[tid]);
    ob[tid + 256] = __float2bfloat16_rn(v1 * r * g[tid + 256]);
}

// ---------------- mma helpers ----------------
__device__ __forceinline__ void mma_bf16(float* d, const unsigned* a, unsigned b0, unsigned b1) {
    asm volatile(
        "mma.sync.aligned.m16n8k16.row.col.f32.bf16.bf16.f32 "
        "{%0,%1,%2,%3}, {%4,%5,%6,%7}, {%8,%9}, {%0,%1,%2,%3};"
        : "+f"(d[0]), "+f"(d[1]), "+f"(d[2]), "+f"(d[3])
        : "r"(a[0]), "r"(a[1]), "r"(a[2]), "r"(a[3]), "r"(b0), "r"(b1));
}
__device__ __forceinline__ unsigned packbf(float lo, float hi) {
    unsigned d;
    asm("cvt.rn.bf16x2.f32 %0, %1, %2;" : "=r"(d) : "f"(hi), "f"(lo));
    return d;
}
__device__ __forceinline__ float ex2f(float x) {
    float y;
    asm("ex2.approx.f32 %0, %1;" : "=f"(y) : "f"(x));
    return y;
}

#define QASTR 40    // A smem row pitch (bf16): 32 + 8 pad
#define QBSTR 136   // B smem row pitch (bf16): 128 + 8 pad

// ---------------- bf16 QKV projection GEMM (head-blocked B and C) ----------------
// Per-sel A pointers: sel picks (A, B, C) triple. 128x128 tile, BK=32.
__global__ __launch_bounds__(256) void gemm_qkv_bf(
    const __nv_bfloat16* __restrict__ A0, const __nv_bfloat16* __restrict__ A1,
    const __nv_bfloat16* __restrict__ A2,
    const float* __restrict__ B0, const float* __restrict__ B1, const float* __restrict__ B2,
    __nv_bfloat16* __restrict__ C0, __nv_bfloat16* __restrict__ C1, __nv_bfloat16* __restrict__ C2,
    int nColBlk)
{
    __shared__ __nv_bfloat16 As[2][128 * QASTR];
    __shared__ __nv_bfloat16 Bs[2][32 * QBSTR];

    int sel  = blockIdx.x / nColBlk;
    int colb = blockIdx.x - sel * nColBlk;
    const __nv_bfloat16* A = (sel == 0) ? A0 : (sel == 1) ? A1 : A2;
    const float* B = (sel == 0) ? B0 : (sel == 1) ? B1 : B2;
    __nv_bfloat16* Cp = ((sel == 0) ? C0 : (sel == 1) ? C1 : C2)
                        + (long)blockIdx.z * H_ * T_ * HS_;

    const __nv_bfloat16* Ab = A + (long)blockIdx.z * T_ * C_ + (long)(blockIdx.y * 128) * C_;
    int col0 = colb * 128;

    int tid = threadIdx.x, lane = tid & 31, w = tid >> 5;
    int g = lane >> 2, t4 = lane & 3;
    int wm = w & 1, wn = w >> 1;

    float acc[4][4][4];
    #pragma unroll
    for (int i = 0; i < 4; i++)
        #pragma unroll
        for (int j = 0; j < 4; j++)
            #pragma unroll
            for (int q = 0; q < 4; q++) acc[i][j][q] = 0.f;

    auto cpA = [&](int st, int k0) {
        #pragma unroll
        for (int j = 0; j < 2; j++) {
            int c = tid * 2 + j;
            int row = c >> 2, kc = (c & 3) * 8;
            cp16(&As[st][row * QASTR + kc], Ab + (long)row * C_ + k0 + kc);
        }
    };

    int bk = tid >> 3;
    int bn0 = (tid & 7) * 16;
    float4 bp[4];
    auto ldB = [&](int k0) {
        #pragma unroll
        for (int jj = 0; jj < 4; jj++) {
            int gc = col0 + bn0 + jj * 4;
            bp[jj] = *reinterpret_cast<const float4*>(
                &B[(long)(gc >> 6) * C_ * HS_ + (long)(k0 + bk) * HS_ + (gc & 63)]);
        }
    };
    auto stB = [&](int st) {
        #pragma unroll
        for (int jj = 0; jj < 4; jj++) {
            uint2 u = { packbf(bp[jj].x, bp[jj].y), packbf(bp[jj].z, bp[jj].w) };
            *reinterpret_cast<uint2*>(&Bs[st][bk * QBSTR + bn0 + jj * 4]) = u;
        }
    };

    int a_lrow = lane & 15, a_lk = (lane >> 4) * 8;
    int b_lrow = ((lane >> 3) & 1) * 8 + (lane & 7), b_lc = (lane >> 4) * 8;

    cpA(0, 0); CP_COMMIT();
    ldB(0);

    #pragma unroll 1
    for (int kt = 0; kt < C_ / 32; kt++) {
        int s = kt & 1;
        CP_WAIT(0);
        stB(s);
        __syncthreads();
        if (kt + 1 < C_ / 32) {
            cpA(s ^ 1, (kt + 1) * 32);
            CP_COMMIT();
            ldB((kt + 1) * 32);
        }

        #pragma unroll
        for (int kc = 0; kc < 32; kc += 16) {
            unsigned afr[4][4];
            #pragma unroll
            for (int mi = 0; mi < 4; mi++) {
                int m0 = wm * 64 + mi * 16;
                unsigned addr = sm_u32(&As[s][(m0 + a_lrow) * QASTR + kc + a_lk]);
                asm volatile(
                    "ldmatrix.sync.aligned.m8n8.x4.shared.b16 {%0,%1,%2,%3}, [%4];"
                    : "=r"(afr[mi][0]), "=r"(afr[mi][1]), "=r"(afr[mi][2]), "=r"(afr[mi][3])
                    : "r"(addr));
            }
            #pragma unroll
            for (int gi = 0; gi < 2; gi++) {
                int n0 = wn * 32 + gi * 16;
                unsigned r0, r1, r2, r3;
                unsigned addr = sm_u32(&Bs[s][(kc + b_lrow) * QBSTR + n0 + b_lc]);
                asm volatile(
                    "ldmatrix.sync.aligned.m8n8.x4.trans.shared.b16 {%0,%1,%2,%3}, [%4];"
                    : "=r"(r0), "=r"(r1), "=r"(r2), "=r"(r3) : "r"(addr));
                #pragma unroll
                for (int mi = 0; mi < 4; mi++) {
                    mma_bf16(acc[mi][2 * gi],     afr[mi], r0, r1);
                    mma_bf16(acc[mi][2 * gi + 1], afr[mi], r2, r3);
                }
            }
        }
    }

    int row0 = blockIdx.y * 128;
    #pragma unroll
    for (int mi = 0; mi < 4; mi++) {
        #pragma unroll
        for (int ni = 0; ni < 4; ni++) {
            int r0 = row0 + wm * 64 + mi * 16 + g;
            int c  = col0 + wn * 32 + ni * 8 + t4 * 2;
            long hb = (long)(c >> 6) * T_ * HS_ + (c & 63);
            #pragma unroll
            for (int half = 0; half < 2; half++) {
                int rr = r0 + half * 8;
                *reinterpret_cast<unsigned*>(&Cp[hb + (long)rr * HS_]) =
                    packbf(acc[mi][ni][half * 2 + 0], acc[mi][ni][half * 2 + 1]);
            }
        }
    }
}

// ---------------- bf16 dense GEMM (plain layouts): O-proj / FFN ----------------
// Tile: 128 rows x (64*NI) cols. NI=2: original 128-wide. NI=1: 64-wide (2x CTAs,
// same total B traffic — use for launches that would otherwise be <148 CTAs).
// resid != null: Cf = resid + v. else accumulate: Cf += v. else Cb = bf16(v).
template<int NI>
__global__ __launch_bounds__(256) void gemm_bf(
    int K,
    const __nv_bfloat16* __restrict__ A, int lda,
    const float* __restrict__ B, int ldb,
    const float* __restrict__ bias,
    float* __restrict__ Cf, __nv_bfloat16* __restrict__ Cb,
    const float* __restrict__ resid,
    int ldc, int accumulate, int gelu_act)
{
    constexpr int BSTR = 64 * NI + 8;
    __shared__ __nv_bfloat16 As[2][128 * QASTR];
    __shared__ __nv_bfloat16 Bs[2][32 * BSTR];

    int row0 = blockIdx.y * 128;
    int col0 = blockIdx.x * 64 * NI;

    int tid = threadIdx.x, lane = tid & 31, w = tid >> 5;
    int g = lane >> 2, t4 = lane & 3;
    int wm = w & 1, wn = w >> 1;

    float acc[4][2 * NI][4];
    #pragma unroll
    for (int i = 0; i < 4; i++)
        #pragma unroll
        for (int j = 0; j < 2 * NI; j++)
            #pragma unroll
            for (int q = 0; q < 4; q++) acc[i][j][q] = 0.f;

    const __nv_bfloat16* Ab = A + (long)row0 * lda;

    auto cpA = [&](int st, int k0) {
        #pragma unroll
        for (int j = 0; j < 2; j++) {
            int c = tid * 2 + j;
            int row = c >> 2, kc = (c & 3) * 8;
            cp16(&As[st][row * QASTR + kc], Ab + (long)row * lda + k0 + kc);
        }
    };

    int bk = tid >> 3;
    int bn0 = (tid & 7) * 8 * NI;
    float4 bp[2 * NI];
    auto ldB = [&](int k0) {
        #pragma unroll
        for (int jj = 0; jj < 2 * NI; jj++)
            bp[jj] = *reinterpret_cast<const float4*>(
                &B[(long)(k0 + bk) * ldb + col0 + bn0 + jj * 4]);
    };
    auto stB = [&](int st) {
        #pragma unroll
        for (int jj = 0; jj < 2 * NI; jj++) {
            uint2 u = { packbf(bp[jj].x, bp[jj].y), packbf(bp[jj].z, bp[jj].w) };
            *reinterpret_cast<uint2*>(&Bs[st][bk * BSTR + bn0 + jj * 4]) = u;
        }
    };

    int a_lrow = lane & 15, a_lk = (lane >> 4) * 8;
    int b_lrow = ((lane >> 3) & 1) * 8 + (lane & 7), b_lc = (lane >> 4) * 8;

    cpA(0, 0); CP_COMMIT();
    ldB(0);

    int nK = K / 32;
    #pragma unroll 1
    for (int kt = 0; kt < nK; kt++) {
        int s = kt & 1;
        CP_WAIT(0);
        stB(s);
        __syncthreads();
        if (kt + 1 < nK) {
            cpA(s ^ 1, (kt + 1) * 32);
            CP_COMMIT();
            ldB((kt + 1) * 32);
        }

        #pragma unroll
        for (int kc = 0; kc < 32; kc += 16) {
            unsigned afr[4][4];
            #pragma unroll
            for (int mi = 0; mi < 4; mi++) {
                int m0 = wm * 64 + mi * 16;
                unsigned addr = sm_u32(&As[s][(m0 + a_lrow) * QASTR + kc + a_lk]);
                asm volatile(
                    "ldmatrix.sync.aligned.m8n8.x4.shared.b16 {%0,%1,%2,%3}, [%4];"
                    : "=r"(afr[mi][0]), "=r"(afr[mi][1]), "=r"(afr[mi][2]), "=r"(afr[mi][3])
                    : "r"(addr));
            }
            #pragma unroll
            for (int gi = 0; gi < NI; gi++) {
                int n0 = wn * 16 * NI + gi * 16;
                unsigned r0, r1, r2, r3;
                unsigned addr = sm_u32(&Bs[s][(kc + b_lrow) * BSTR + n0 + b_lc]);
                asm volatile(
                    "ldmatrix.sync.aligned.m8n8.x4.trans.shared.b16 {%0,%1,%2,%3}, [%4];"
                    : "=r"(r0), "=r"(r1), "=r"(r2), "=r"(r3) : "r"(addr));
                #pragma unroll
                for (int mi = 0; mi < 4; mi++) {
                    mma_bf16(acc[mi][2 * gi],     afr[mi], r0, r1);
                    mma_bf16(acc[mi][2 * gi + 1], afr[mi], r2, r3);
                }
            }
        }
    }

    #pragma unroll
    for (int mi = 0; mi < 4; mi++) {
        #pragma unroll
        for (int ni = 0; ni < 2 * NI; ni++) {
            int r0 = row0 + wm * 64 + mi * 16 + g;
            int c  = col0 + wn * 16 * NI + ni * 8 + t4 * 2;
            #pragma unroll
            for (int half = 0; half < 2; half++) {
                int rr = r0 + half * 8;
                float v0 = acc[mi][ni][half * 2 + 0];
                float v1 = acc[mi][ni][half * 2 + 1];
                if (bias) { v0 += bias[c]; v1 += bias[c + 1]; }
                if (gelu_act) {
                    v0 = 0.5f * v0 * (1.0f + erff(v0 * 0.70710678118654752f));
                    v1 = 0.5f * v1 * (1.0f + erff(v1 * 0.70710678118654752f));
                }
                if (resid) {
                    const float* rrow = &resid[(long)rr * ldc + c];
                    float* crow = &Cf[(long)rr * ldc + c];
                    crow[0] = rrow[0] + v0; crow[1] = rrow[1] + v1;
                } else if (accumulate) {
                    float* crow = &Cf[(long)rr * ldc + c];
                    crow[0] += v0; crow[1] += v1;
                } else {
                    *reinterpret_cast<unsigned*>(&Cb[(long)rr * ldc + c]) = packbf(v0, v1);
                }
            }
        }
    }
}

// ---------------- fused flash attention (bf16 mma, ldmatrix frags, exp2 softmax) ----------------
// (R9 mainloop — known good; only the q-block -> blockIdx mapping changed:
//  causal launches process heavy (large q0) blocks FIRST for wave balance.)
#define KVW 72
#define CEXP 0.18033688011112042f   // 0.125 * log2(e)

__global__ __launch_bounds__(256, 2) void flash_bf(
    const __nv_bfloat16* __restrict__ Qg,
    const __nv_bfloat16* __restrict__ Kg,
    const __nv_bfloat16* __restrict__ Vg,
    __nv_bfloat16* __restrict__ Out,
    int causal)
{
    __shared__ __nv_bfloat16 Ks[2][64 * KVW];
    __shared__ __nv_bfloat16 Vs[2][64 * KVW];

    int bh = blockIdx.y;
    int b = bh >> 3, h = bh & 7;
    int qblk = causal ? (gridDim.x - 1 - blockIdx.x) : blockIdx.x;
    int q0 = qblk * 128;
    long base = (long)bh * T_ * HS_;
    const __nv_bfloat16* Qb = Qg + base;
    const __nv_bfloat16* Kb = Kg + base;
    const __nv_bfloat16* Vb = Vg + base;

    int tid = threadIdx.x;
    int lane = tid & 31, w = tid >> 5;
    int g = lane >> 2, t4 = lane & 3;
    int wr = w * 16;

    auto loadKV = [&](int st, int s0) {
        #pragma unroll
        for (int j = 0; j < 2; j++) {
            int c = tid + j * 256;
            int row = c >> 3;
            int cc = (c & 7) * 8;
            cp16(&Ks[st][row * KVW + cc], Kb + (long)(s0 + row) * HS_ + cc);
            cp16(&Vs[st][row * KVW + cc], Vb + (long)(s0 + row) * HS_ + cc);
        }
    };

    unsigned Qa[4][4];
    {
        const __nv_bfloat16* q0p = Qb + (long)(q0 + wr + g) * HS_;
        const __nv_bfloat16* q1p = q0p + 8 * HS_;
        #pragma unroll
        for (int c = 0; c < 4; c++) {
            Qa[c][0] = *reinterpret_cast<const unsigned*>(&q0p[c * 16 + 2 * t4]);
            Qa[c][1] = *reinterpret_cast<const unsigned*>(&q1p[c * 16 + 2 * t4]);
            Qa[c][2] = *reinterpret_cast<const unsigned*>(&q0p[c * 16 + 8 + 2 * t4]);
            Qa[c][3] = *reinterpret_cast<const unsigned*>(&q1p[c * 16 + 8 + 2 * t4]);
        }
    }

    float Oacc[8][4];
    #pragma unroll
    for (int i = 0; i < 8; i++)
        #pragma unroll
        for (int j = 0; j < 4; j++) Oacc[i][j] = 0.f;
    // m tracked in RAW S units (pre-0.125 scale)
    float m0 = -1e30f, m1 = -1e30f, l0 = 0.f, l1 = 0.f;

    int nT = causal ? (q0 / 64 + 2) : (T_ / 64);

    loadKV(0, 0);
    CP_COMMIT();

    // ldmatrix per-thread offsets
    int lmj = lane >> 3, lmt = lane & 7;
    int vt_off = ((lmj & 1) * 8 + lmt) * KVW + (lmj >> 1) * 8;          // V (trans)
    int kt_row = (lane & 7) + 8 * (lane >> 4);                          // K (non-trans)
    int kt_add = ((lane >> 3) & 1) * 8;

    for (int it = 0; it < nT; it++) {
        int s = it & 1;
        int s0 = it * 64;
        CP_WAIT(0);
        __syncthreads();
        if (it + 1 < nT) {
            loadKV(s ^ 1, (it + 1) * 64);
            CP_COMMIT();
        }

        unsigned kbase = sm_u32(&Ks[s][0]);
        unsigned vbase = sm_u32(&Vs[s][0]);

        // S = Q K^T (raw; scale folded into exp2)
        float S[8][4];
        #pragma unroll
        for (int nf = 0; nf < 8; nf++)
            #pragma unroll
            for (int j = 0; j < 4; j++) S[nf][j] = 0.f;

        #pragma unroll
        for (int c = 0; c < 4; c++) {
            #pragma unroll
            for (int nfp = 0; nfp < 4; nfp++) {
                unsigned r0, r1, r2, r3;
                unsigned addr = kbase + (unsigned)(((nfp * 16 + kt_row) * KVW + c * 16 + kt_add) * 2);
                asm volatile(
                    "ldmatrix.sync.aligned.m8n8.x4.shared.b16 {%0,%1,%2,%3}, [%4];"
                    : "=r"(r0), "=r"(r1), "=r"(r2), "=r"(r3) : "r"(addr));
                mma_bf16(S[2 * nfp],     Qa[c], r0, r1);
                mma_bf16(S[2 * nfp + 1], Qa[c], r2, r3);
            }
        }

        // causal mask (diagonal tiles only)
        if (causal && (s0 + 63 > q0 + wr)) {
            int r0g = q0 + wr + g;
            #pragma unroll
            for (int nf = 0; nf < 8; nf++) {
                int cbase = s0 + nf * 8 + 2 * t4;
                if (cbase     > r0g)     S[nf][0] = -1e30f;
                if (cbase + 1 > r0g)     S[nf][1] = -1e30f;
                if (cbase     > r0g + 8) S[nf][2] = -1e30f;
                if (cbase + 1 > r0g + 8) S[nf][3] = -1e30f;
            }
        }

        // row max (raw units), reduce over t4 quad
        float tm0 = -1e30f, tm1 = -1e30f;
        #pragma unroll
        for (int nf = 0; nf < 8; nf++) {
            tm0 = fmaxf(tm0, fmaxf(S[nf][0], S[nf][1]));
            tm1 = fmaxf(tm1, fmaxf(S[nf][2], S[nf][3]));
        }
        tm0 = fmaxf(tm0, __shfl_xor_sync(0xffffffffu, tm0, 1));
        tm0 = fmaxf(tm0, __shfl_xor_sync(0xffffffffu, tm0, 2));
        tm1 = fmaxf(tm1, __shfl_xor_sync(0xffffffffu, tm1, 1));
        tm1 = fmaxf(tm1, __shfl_xor_sync(0xffffffffu, tm1, 2));

        float nm0 = fmaxf(m0, tm0), nm1 = fmaxf(m1, tm1);
        float f0 = ex2f((m0 - nm0) * CEXP), f1 = ex2f((m1 - nm1) * CEXP);

        float rs0 = 0.f, rs1 = 0.f;
        #pragma unroll
        for (int nf = 0; nf < 8; nf++) {
            S[nf][0] = ex2f((S[nf][0] - nm0) * CEXP);
            S[nf][1] = ex2f((S[nf][1] - nm0) * CEXP);
            S[nf][2] = ex2f((S[nf][2] - nm1) * CEXP);
            S[nf][3] = ex2f((S[nf][3] - nm1) * CEXP);
            rs0 += S[nf][0] + S[nf][1];
            rs1 += S[nf][2] + S[nf][3];
        }
        rs0 += __shfl_xor_sync(0xffffffffu, rs0, 1);
        rs0 += __shfl_xor_sync(0xffffffffu, rs0, 2);
        rs1 += __shfl_xor_sync(0xffffffffu, rs1, 1);
        rs1 += __shfl_xor_sync(0xffffffffu, rs1, 2);

        l0 = l0 * f0 + rs0;
        l1 = l1 * f1 + rs1;
        m0 = nm0; m1 = nm1;

        #pragma unroll
        for (int nf = 0; nf < 8; nf++) {
            Oacc[nf][0] *= f0; Oacc[nf][1] *= f0;
            Oacc[nf][2] *= f1; Oacc[nf][3] *= f1;
        }

        // O += P V : A-frags packed from S; B-frags via ldmatrix.trans
        #pragma unroll
        for (int c = 0; c < 4; c++) {
            unsigned a4[4];
            a4[0] = packbf(S[2 * c][0],     S[2 * c][1]);
            a4[1] = packbf(S[2 * c][2],     S[2 * c][3]);
            a4[2] = packbf(S[2 * c + 1][0], S[2 * c + 1][1]);
            a4[3] = packbf(S[2 * c + 1][2], S[2 * c + 1][3]);
            #pragma unroll
            for (int gi = 0; gi < 4; gi++) {
                unsigned r0, r1, r2, r3;
                unsigned addr = vbase + (unsigned)((c * 16 * KVW + gi * 16 + vt_off) * 2);
                asm volatile(
                    "ldmatrix.sync.aligned.m8n8.x4.trans.shared.b16 {%0,%1,%2,%3}, [%4];"
                    : "=r"(r0), "=r"(r1), "=r"(r2), "=r"(r3) : "r"(addr));
                mma_bf16(Oacc[2 * gi],     a4, r0, r1);
                mma_bf16(Oacc[2 * gi + 1], a4, r2, r3);
            }
        }
    }

    // epilogue: normalize and write bf16 [B,T,C]
    float inv0 = 1.f / l0, inv1 = 1.f / l1;
    __nv_bfloat16* o0 = Out + ((long)b * T_ + q0 + wr + g) * C_ + h * HS_;
    __nv_bfloat16* o1 = Out + ((long)b * T_ + q0 + wr + g + 8) * C_ + h * HS_;
    #pragma unroll
    for (int nf = 0; nf < 8; nf++) {
        int c = nf * 8 + 2 * t4;
        *reinterpret_cast<unsigned*>(&o0[c]) = packbf(Oacc[nf][0] * inv0, Oacc[nf][1] * inv0);
        *reinterpret_cast<unsigned*>(&o1[c]) = packbf(Oacc[nf][2] * inv1, Oacc[nf][3] * inv1);
    }
}

// ---------------- orchestration ----------------
extern "C" void kernel_launch(void* const* d_in, const int* in_sizes, int n_in,
                              void* d_out, int out_size)
{
    const float* hidden = (const float*)d_in[0];
    const float* target = (const float*)d_in[1];
    const float* Wq_s = (const float*)d_in[2];
    const float* Wk_s = (const float*)d_in[3];
    const float* Wv_s = (const float*)d_in[4];
    const float* Wo_s = (const float*)d_in[5];
    const float* bo_s = (const float*)d_in[6];
    const float* Wq_x = (const float*)d_in[7];
    const float* Wk_x = (const float*)d_in[8];
    const float* Wv_x = (const float*)d_in[9];
    const float* Wo_x = (const float*)d_in[10];
    const float* bo_x = (const float*)d_in[11];
    const float* W1 = (const float*)d_in[12];
    const float* b1 = (const float*)d_in[13];
    const float* W2 = (const float*)d_in[14];
    const float* b2 = (const float*)d_in[15];
    const float* g1 = (const float*)d_in[16];
    const float* g2 = (const float*)d_in[17];
    const float* g3 = (const float*)d_in[18];
    const float* g4 = (const float*)d_in[19];

    float* t = (float*)d_out;

    __nv_bfloat16 *xnb, *hnb, *qb, *kb, *vb, *attnb, *ffb;
    cudaGetSymbolAddress((void**)&xnb, g_xnb);
    cudaGetSymbolAddress((void**)&hnb, g_hnb);
    cudaGetSymbolAddress((void**)&qb, g_q);
    cudaGetSymbolAddress((void**)&kb, g_k);
    cudaGetSymbolAddress((void**)&vb, g_v);
    cudaGetSymbolAddress((void**)&attnb, g_attnb);
    cudaGetSymbolAddress((void**)&ffb, g_ffb);

    const long HCHS = (long)H_ * C_ * HS_;   // per-layer weight stride

    dim3 gQKV(12, T_ / 128, NB);             // 3 sels x 4 col-blocks, z=b
    dim3 gO(C_ / 64, BT_ / 128, 1);          // 256 CTAs (NI=1)
    dim3 gF1(FF_ / 128, BT_ / 128, 1);       // 256 CTAs (NI=2)
    dim3 gF2(C_ / 64, BT_ / 128, 1);         // 256 CTAs (NI=1)
    dim3 gFl(T_ / 128, BH_, 1);

    for (int l = 0; l < NL; l++) {
        // ======== masked self-attention ========
        // layer 0: residual stream is still `target` (t not yet written)
        const float* tcur = (l == 0) ? target : t;
        rmsnorm_k<<<BT_, 256>>>(tcur, g1 + (long)l * C_, xnb);

        gemm_qkv_bf<<<gQKV, 256>>>(xnb, xnb, xnb,
            Wq_s + l * HCHS, Wk_s + l * HCHS, Wv_s + l * HCHS,
            qb, kb, vb, 4);

        flash_bf<<<gFl, 256>>>(qb, kb, vb, attnb, 1);

        gemm_bf<1><<<gO, 256>>>(C_,
            attnb, C_,
            Wo_s + (long)l * C_ * C_, C_,
            bo_s + (long)l * C_,
            t, nullptr, (l == 0) ? target : nullptr,
            C_, (l == 0) ? 0 : 1, 0);

        // ======== cross-attention (Q + K/V fused into one launch) ========
        rmsnorm_k<<<BT_, 256>>>(hidden, g2 + (long)l * C_, hnb);
        rmsnorm_k<<<BT_, 256>>>(t, g3 + (long)l * C_, xnb);

        gemm_qkv_bf<<<gQKV, 256>>>(xnb, hnb, hnb,
            Wq_x + l * HCHS, Wk_x + l * HCHS, Wv_x + l * HCHS,
            qb, kb, vb, 4);

        flash_bf<<<gFl, 256>>>(qb, kb, vb, attnb, 0);

        gemm_bf<1><<<gO, 256>>>(C_,
            attnb, C_,
            Wo_x + (long)l * C_ * C_, C_,
            bo_x + (long)l * C_,
            t, nullptr, nullptr,
            C_, 1, 0);

        // ======== GELU FFN ========
        rmsnorm_k<<<BT_, 256>>>(t, g4 + (long)l * C_, xnb);

        gemm_bf<2><<<gF1, 256>>>(C_,
            xnb, C_,
            W1 + (long)l * C_ * FF_, FF_,
            b1 + (long)l * FF_,
            nullptr, ffb, nullptr,
            FF_, 0, 1);

        gemm_bf<1><<<gF2, 256>>>(FF_,
            ffb, FF_,
            W2 + (long)l * FF_ * C_, C_,
            b2 + (long)l * C_,
            t, nullptr, nullptr,
            C_, 1, 0);
    }
}

// round 17
// speedup vs baseline: 1.7639x; 1.0720x over previous
#include <cuda_runtime.h>
#include <cuda_bf16.h>
#include <math.h>

// Problem dims
#define NL  2
#define NB  2
#define T_  2048
#define C_  512
#define H_  8
#define FF_ 1024
#define HS_ 64
#define EPS_ 1.1920929e-07f

#define BT_  (NB * T_)        // 4096 rows
#define BTC_ (NB * T_ * C_)   // 2097152
#define BH_  (NB * H_)        // 16

// weight-buffer layout (bf16), per layer
#define WOFF_QS 0
#define WOFF_KS 262144
#define WOFF_VS 524288
#define WOFF_OS 786432
#define WOFF_QX 1048576
#define WOFF_KX 1310720
#define WOFF_VX 1572864
#define WOFF_OX 1835008
#define WOFF_W1 2097152
#define WOFF_W2 2621440
#define WLAYER  3145728

// ---------------- scratch ----------------
__device__ __nv_bfloat16 g_xnb[BTC_];    // bf16 normed activations
__device__ __nv_bfloat16 g_hnb[BTC_];
__device__ __nv_bfloat16 g_q[BTC_];      // [B,H,T,HS] bf16
__device__ __nv_bfloat16 g_k[BTC_];
__device__ __nv_bfloat16 g_v[BTC_];
__device__ __nv_bfloat16 g_attnb[BTC_];  // [B,T,C] bf16 (flash out)
__device__ __nv_bfloat16 g_ffb[NB * T_ * FF_];
__device__ __nv_bfloat16 g_wb[NL * WLAYER];  // converted weights (12 MB)

// ---------------- cp.async helpers ----------------
__device__ __forceinline__ unsigned sm_u32(const void* p) {
    return (unsigned)__cvta_generic_to_shared(p);
}
__device__ __forceinline__ void cp16(void* dst_smem, const void* src) {
    asm volatile("cp.async.cg.shared.global [%0], [%1], 16;"
                 :: "r"(sm_u32(dst_smem)), "l"(src));
}
#define CP_COMMIT() asm volatile("cp.async.commit_group;")
#define CP_WAIT(n)  asm volatile("cp.async.wait_group %0;" :: "n"(n))

// ---------------- mma helpers ----------------
__device__ __forceinline__ void mma_bf16(float* d, const unsigned* a, unsigned b0, unsigned b1) {
    asm volatile(
        "mma.sync.aligned.m16n8k16.row.col.f32.bf16.bf16.f32 "
        "{%0,%1,%2,%3}, {%4,%5,%6,%7}, {%8,%9}, {%0,%1,%2,%3};"
        : "+f"(d[0]), "+f"(d[1]), "+f"(d[2]), "+f"(d[3])
        : "r"(a[0]), "r"(a[1]), "r"(a[2]), "r"(a[3]), "r"(b0), "r"(b1));
}
__device__ __forceinline__ unsigned packbf(float lo, float hi) {
    unsigned d;
    asm("cvt.rn.bf16x2.f32 %0, %1, %2;" : "=r"(d) : "f"(hi), "f"(lo));
    return d;
}
__device__ __forceinline__ float ex2f(float x) {
    float y;
    asm("ex2.approx.f32 %0, %1;" : "=f"(y) : "f"(x));
    return y;
}

// ---------------- weight conversion: fp32 -> bf16 (QKV re-laid to [C][512]) ----------------
__global__ __launch_bounds__(256) void convw_k(
    const float* __restrict__ Wq_s, const float* __restrict__ Wk_s,
    const float* __restrict__ Wv_s, const float* __restrict__ Wo_s,
    const float* __restrict__ Wq_x, const float* __restrict__ Wk_x,
    const float* __restrict__ Wv_x, const float* __restrict__ Wo_x,
    const float* __restrict__ W1,   const float* __restrict__ W2,
    __nv_bfloat16* __restrict__ out)
{
    int z = blockIdx.z;        // tensor 0..9
    int l = blockIdx.y;        // layer

    const float* src =
        (z == 0) ? Wq_s : (z == 1) ? Wk_s : (z == 2) ? Wv_s : (z == 3) ? Wo_s :
        (z == 4) ? Wq_x : (z == 5) ? Wk_x : (z == 6) ? Wv_x : (z == 7) ? Wo_x :
        (z == 8) ? W1 : W2;
    long sz   = (z >= 8) ? 524288 : 262144;
    long off  = (z == 0) ? WOFF_QS : (z == 1) ? WOFF_KS : (z == 2) ? WOFF_VS :
                (z == 3) ? WOFF_OS : (z == 4) ? WOFF_QX : (z == 5) ? WOFF_KX :
                (z == 6) ? WOFF_VX : (z == 7) ? WOFF_OX : (z == 8) ? WOFF_W1 : WOFF_W2;
    int headed = (z <= 2) || (z >= 4 && z <= 6);

    src += (long)l * sz;
    __nv_bfloat16* dst = out + (long)l * WLAYER + off;

    long idx = (long)blockIdx.x * 256 + threadIdx.x;   // 8 elems per thread
    if (idx * 8 >= sz) return;

    long inoff, outoff;
    if (headed) {
        // src [H][C][HS] -> dst [C][H*HS]
        int h   = (int)(idx >> 12);
        int k   = (int)((idx >> 3) & (C_ - 1));
        int hs0 = (int)(idx & 7) * 8;
        inoff  = (long)h * C_ * HS_ + (long)k * HS_ + hs0;
        outoff = (long)k * 512 + h * HS_ + hs0;
    } else {
        inoff = outoff = idx * 8;
    }
    float4 a = *reinterpret_cast<const float4*>(src + inoff);
    float4 b = *reinterpret_cast<const float4*>(src + inoff + 4);
    uint4 u = { packbf(a.x, a.y), packbf(a.z, a.w), packbf(b.x, b.y), packbf(b.z, b.w) };
    *reinterpret_cast<uint4*>(dst + outoff) = u;
}

// ---------------- rmsnorm -> bf16 (single and dual) ----------------
__device__ __forceinline__ void rms_body(
    const float* __restrict__ xr, const float* __restrict__ g,
    __nv_bfloat16* __restrict__ ob, int tid)
{
    float v0 = xr[tid];
    float v1 = xr[tid + 256];
    float ss = v0 * v0 + v1 * v1;

    __shared__ float red[8];
    #pragma unroll
    for (int o = 16; o; o >>= 1) ss += __shfl_xor_sync(0xffffffffu, ss, o);
    if ((tid & 31) == 0) red[tid >> 5] = ss;
    __syncthreads();
    if (tid == 0) {
        float s = 0.f;
        #pragma unroll
        for (int w = 0; w < 8; w++) s += red[w];
        red[0] = rsqrtf(s * (1.0f / C_) + EPS_);
    }
    __syncthreads();
    float r = red[0];
    ob[tid]       = __float2bfloat16_rn(v0 * r * g[tid]);
    ob[tid + 256] = __float2bfloat16_rn(v1 * r * g[tid + 256]);
}

__global__ __launch_bounds__(256) void rmsnorm_k(
    const float* __restrict__ x, const float* __restrict__ g,
    __nv_bfloat16* __restrict__ outb)
{
    long row = blockIdx.x;
    rms_body(x + row * C_, g, outb + row * C_, threadIdx.x);
}

__global__ __launch_bounds__(256) void rmsnorm2_k(
    const float* __restrict__ x0, const float* __restrict__ g0, __nv_bfloat16* __restrict__ o0,
    const float* __restrict__ x1, const float* __restrict__ g1, __nv_bfloat16* __restrict__ o1)
{
    long row = blockIdx.x;
    if (blockIdx.y == 0) rms_body(x0 + row * C_, g0, o0 + row * C_, threadIdx.x);
    else                 rms_body(x1 + row * C_, g1, o1 + row * C_, threadIdx.x);
}

#define QASTR 40    // A smem row pitch (bf16): 32 + 8 pad
#define QBSTR 136   // B smem row pitch (bf16): 128 + 8 pad (128-wide tiles)

// ---------------- bf16 QKV projection GEMM (plain bf16 B, head-blocked C) ----------------
// 3-stage all-cp.async pipeline. B: [C][512] bf16 (converted). C: [B,H,T,HS] bf16.
#define QKV_SMEM ((3 * 128 * QASTR + 3 * 32 * QBSTR) * 2)
__global__ __launch_bounds__(256) void gemm_qkv_bf(
    const __nv_bfloat16* __restrict__ A0, const __nv_bfloat16* __restrict__ A1,
    const __nv_bfloat16* __restrict__ A2,
    const __nv_bfloat16* __restrict__ B0, const __nv_bfloat16* __restrict__ B1,
    const __nv_bfloat16* __restrict__ B2,
    __nv_bfloat16* __restrict__ C0, __nv_bfloat16* __restrict__ C1,
    __nv_bfloat16* __restrict__ C2,
    int nColBlk)
{
    extern __shared__ __nv_bfloat16 dsm[];
    __nv_bfloat16* AsB = dsm;                     // [3][128*QASTR]
    __nv_bfloat16* BsB = dsm + 3 * 128 * QASTR;   // [3][32*QBSTR]

    int sel  = blockIdx.x / nColBlk;
    int colb = blockIdx.x - sel * nColBlk;
    const __nv_bfloat16* A = (sel == 0) ? A0 : (sel == 1) ? A1 : A2;
    const __nv_bfloat16* Bb = (sel == 0) ? B0 : (sel == 1) ? B1 : B2;
    __nv_bfloat16* Cp = ((sel == 0) ? C0 : (sel == 1) ? C1 : C2)
                        + (long)blockIdx.z * H_ * T_ * HS_;

    const __nv_bfloat16* Ab = A + (long)blockIdx.z * T_ * C_ + (long)(blockIdx.y * 128) * C_;
    int col0 = colb * 128;

    int tid = threadIdx.x, lane = tid & 31, w = tid >> 5;
    int g = lane >> 2, t4 = lane & 3;
    int wm = w & 1, wn = w >> 1;

    float acc[4][4][4];
    #pragma unroll
    for (int i = 0; i < 4; i++)
        #pragma unroll
        for (int j = 0; j < 4; j++)
            #pragma unroll
            for (int q = 0; q < 4; q++) acc[i][j][q] = 0.f;

    auto cpA = [&](int st, int k0) {
        __nv_bfloat16* As = AsB + st * 128 * QASTR;
        #pragma unroll
        for (int j = 0; j < 2; j++) {
            int c = tid * 2 + j;
            int row = c >> 2, kc = (c & 3) * 8;
            cp16(&As[row * QASTR + kc], Ab + (long)row * C_ + k0 + kc);
        }
    };
    auto cpB = [&](int st, int k0) {
        __nv_bfloat16* Bs = BsB + st * 32 * QBSTR;
        #pragma unroll
        for (int j = 0; j < 2; j++) {
            int c = tid * 2 + j;
            int kk = c >> 4, n8 = (c & 15) * 8;
            cp16(&Bs[kk * QBSTR + n8], Bb + (long)(k0 + kk) * 512 + col0 + n8);
        }
    };

    int a_lrow = lane & 15, a_lk = (lane >> 4) * 8;
    int b_lrow = ((lane >> 3) & 1) * 8 + (lane & 7), b_lc = (lane >> 4) * 8;

    const int nK = C_ / 32;   // 16
    cpA(0, 0);  cpB(0, 0);  CP_COMMIT();
    cpA(1, 32); cpB(1, 32); CP_COMMIT();

    #pragma unroll 1
    for (int kt = 0; kt < nK; kt++) {
        int s = kt % 3;
        if (kt + 1 < nK) { CP_WAIT(1); } else { CP_WAIT(0); }
        __syncthreads();
        if (kt + 2 < nK) {
            cpA((kt + 2) % 3, (kt + 2) * 32);
            cpB((kt + 2) % 3, (kt + 2) * 32);
            CP_COMMIT();
        }

        const __nv_bfloat16* As = AsB + s * 128 * QASTR;
        const __nv_bfloat16* Bs = BsB + s * 32 * QBSTR;

        #pragma unroll
        for (int kc = 0; kc < 32; kc += 16) {
            unsigned afr[4][4];
            #pragma unroll
            for (int mi = 0; mi < 4; mi++) {
                int m0 = wm * 64 + mi * 16;
                unsigned addr = sm_u32(&As[(m0 + a_lrow) * QASTR + kc + a_lk]);
                asm volatile(
                    "ldmatrix.sync.aligned.m8n8.x4.shared.b16 {%0,%1,%2,%3}, [%4];"
                    : "=r"(afr[mi][0]), "=r"(afr[mi][1]), "=r"(afr[mi][2]), "=r"(afr[mi][3])
                    : "r"(addr));
            }
            #pragma unroll
            for (int gi = 0; gi < 2; gi++) {
                int n0 = wn * 32 + gi * 16;
                unsigned r0, r1, r2, r3;
                unsigned addr = sm_u32(&Bs[(kc + b_lrow) * QBSTR + n0 + b_lc]);
                asm volatile(
                    "ldmatrix.sync.aligned.m8n8.x4.trans.shared.b16 {%0,%1,%2,%3}, [%4];"
                    : "=r"(r0), "=r"(r1), "=r"(r2), "=r"(r3) : "r"(addr));
                #pragma unroll
                for (int mi = 0; mi < 4; mi++) {
                    mma_bf16(acc[mi][2 * gi],     afr[mi], r0, r1);
                    mma_bf16(acc[mi][2 * gi + 1], afr[mi], r2, r3);
                }
            }
        }
    }

    int row0 = blockIdx.y * 128;
    #pragma unroll
    for (int mi = 0; mi < 4; mi++) {
        #pragma unroll
        for (int ni = 0; ni < 4; ni++) {
            int r0 = row0 + wm * 64 + mi * 16 + g;
            int c  = col0 + wn * 32 + ni * 8 + t4 * 2;
            long hb = (long)(c >> 6) * T_ * HS_ + (c & 63);
            #pragma unroll
            for (int half = 0; half < 2; half++) {
                int rr = r0 + half * 8;
                *reinterpret_cast<unsigned*>(&Cp[hb + (long)rr * HS_]) =
                    packbf(acc[mi][ni][half * 2 + 0], acc[mi][ni][half * 2 + 1]);
            }
        }
    }
}

// ---------------- bf16 dense GEMM (plain layouts, bf16 B): O-proj / FFN ----------------
// Tile: 128 rows x (64*NI) cols. 3-stage all-cp.async pipeline.
// resid != null: Cf = resid + v. else accumulate: Cf += v. else Cb = bf16(v).
template<int NI>
__global__ __launch_bounds__(256) void gemm_bf(
    int K,
    const __nv_bfloat16* __restrict__ A, int lda,
    const __nv_bfloat16* __restrict__ Bb, int ldb,
    const float* __restrict__ bias,
    float* __restrict__ Cf, __nv_bfloat16* __restrict__ Cb,
    const float* __restrict__ resid,
    int ldc, int accumulate, int gelu_act)
{
    constexpr int BSTR = 64 * NI + 8;
    extern __shared__ __nv_bfloat16 dsm[];
    __nv_bfloat16* AsB = dsm;                     // [3][128*QASTR]
    __nv_bfloat16* BsB = dsm + 3 * 128 * QASTR;   // [3][32*BSTR]

    int row0 = blockIdx.y * 128;
    int col0 = blockIdx.x * 64 * NI;

    int tid = threadIdx.x, lane = tid & 31, w = tid >> 5;
    int g = lane >> 2, t4 = lane & 3;
    int wm = w & 1, wn = w >> 1;

    float acc[4][2 * NI][4];
    #pragma unroll
    for (int i = 0; i < 4; i++)
        #pragma unroll
        for (int j = 0; j < 2 * NI; j++)
            #pragma unroll
            for (int q = 0; q < 4; q++) acc[i][j][q] = 0.f;

    const __nv_bfloat16* Ab = A + (long)row0 * lda;

    auto cpA = [&](int st, int k0) {
        __nv_bfloat16* As = AsB + st * 128 * QASTR;
        #pragma unroll
        for (int j = 0; j < 2; j++) {
            int c = tid * 2 + j;
            int row = c >> 2, kc = (c & 3) * 8;
            cp16(&As[row * QASTR + kc], Ab + (long)row * lda + k0 + kc);
        }
    };
    auto cpB = [&](int st, int k0) {
        __nv_bfloat16* Bs = BsB + st * 32 * BSTR;
        #pragma unroll
        for (int j = 0; j < NI; j++) {
            int c = tid * NI + j;
            int kk, n8;
            if (NI == 2) { kk = c >> 4; n8 = (c & 15) * 8; }
            else         { kk = c >> 3; n8 = (c & 7) * 8; }
            cp16(&Bs[kk * BSTR + n8], Bb + (long)(k0 + kk) * ldb + col0 + n8);
        }
    };

    int a_lrow = lane & 15, a_lk = (lane >> 4) * 8;
    int b_lrow = ((lane >> 3) & 1) * 8 + (lane & 7), b_lc = (lane >> 4) * 8;

    int nK = K / 32;
    cpA(0, 0);  cpB(0, 0);  CP_COMMIT();
    cpA(1, 32); cpB(1, 32); CP_COMMIT();

    #pragma unroll 1
    for (int kt = 0; kt < nK; kt++) {
        int s = kt % 3;
        if (kt + 1 < nK) { CP_WAIT(1); } else { CP_WAIT(0); }
        __syncthreads();
        if (kt + 2 < nK) {
            cpA((kt + 2) % 3, (kt + 2) * 32);
            cpB((kt + 2) % 3, (kt + 2) * 32);
            CP_COMMIT();
        }

        const __nv_bfloat16* As = AsB + s * 128 * QASTR;
        const __nv_bfloat16* Bs = BsB + s * 32 * BSTR;

        #pragma unroll
        for (int kc = 0; kc < 32; kc += 16) {
            unsigned afr[4][4];
            #pragma unroll
            for (int mi = 0; mi < 4; mi++) {
                int m0 = wm * 64 + mi * 16;
                unsigned addr = sm_u32(&As[(m0 + a_lrow) * QASTR + kc + a_lk]);
                asm volatile(
                    "ldmatrix.sync.aligned.m8n8.x4.shared.b16 {%0,%1,%2,%3}, [%4];"
                    : "=r"(afr[mi][0]), "=r"(afr[mi][1]), "=r"(afr[mi][2]), "=r"(afr[mi][3])
                    : "r"(addr));
            }
            #pragma unroll
            for (int gi = 0; gi < NI; gi++) {
                int n0 = wn * 16 * NI + gi * 16;
                unsigned r0, r1, r2, r3;
                unsigned addr = sm_u32(&Bs[(kc + b_lrow) * BSTR + n0 + b_lc]);
                asm volatile(
                    "ldmatrix.sync.aligned.m8n8.x4.trans.shared.b16 {%0,%1,%2,%3}, [%4];"
                    : "=r"(r0), "=r"(r1), "=r"(r2), "=r"(r3) : "r"(addr));
                #pragma unroll
                for (int mi = 0; mi < 4; mi++) {
                    mma_bf16(acc[mi][2 * gi],     afr[mi], r0, r1);
                    mma_bf16(acc[mi][2 * gi + 1], afr[mi], r2, r3);
                }
            }
        }
    }

    #pragma unroll
    for (int mi = 0; mi < 4; mi++) {
        #pragma unroll
        for (int ni = 0; ni < 2 * NI; ni++) {
            int r0 = row0 + wm * 64 + mi * 16 + g;
            int c  = col0 + wn * 16 * NI + ni * 8 + t4 * 2;
            #pragma unroll
            for (int half = 0; half < 2; half++) {
                int rr = r0 + half * 8;
                float v0 = acc[mi][ni][half * 2 + 0];
                float v1 = acc[mi][ni][half * 2 + 1];
                if (bias) { v0 += bias[c]; v1 += bias[c + 1]; }
                if (gelu_act) {
                    v0 = 0.5f * v0 * (1.0f + erff(v0 * 0.70710678118654752f));
                    v1 = 0.5f * v1 * (1.0f + erff(v1 * 0.70710678118654752f));
                }
                if (resid) {
                    const float* rrow = &resid[(long)rr * ldc + c];
                    float* crow = &Cf[(long)rr * ldc + c];
                    crow[0] = rrow[0] + v0; crow[1] = rrow[1] + v1;
                } else if (accumulate) {
                    float* crow = &Cf[(long)rr * ldc + c];
                    crow[0] += v0; crow[1] += v1;
                } else {
                    *reinterpret_cast<unsigned*>(&Cb[(long)rr * ldc + c]) = packbf(v0, v1);
                }
            }
        }
    }
}

// ---------------- fused flash attention (bf16 mma, ldmatrix frags, exp2 softmax) ----------------
// (R12 version — known good; do not perturb.)
#define KVW 72
#define CEXP 0.18033688011112042f   // 0.125 * log2(e)

__global__ __launch_bounds__(256, 2) void flash_bf(
    const __nv_bfloat16* __restrict__ Qg,
    const __nv_bfloat16* __restrict__ Kg,
    const __nv_bfloat16* __restrict__ Vg,
    __nv_bfloat16* __restrict__ Out,
    int causal)
{
    __shared__ __nv_bfloat16 Ks[2][64 * KVW];
    __shared__ __nv_bfloat16 Vs[2][64 * KVW];

    int bh = blockIdx.y;
    int b = bh >> 3, h = bh & 7;
    int qblk = causal ? (gridDim.x - 1 - blockIdx.x) : blockIdx.x;
    int q0 = qblk * 128;
    long base = (long)bh * T_ * HS_;
    const __nv_bfloat16* Qb = Qg + base;
    const __nv_bfloat16* Kb = Kg + base;
    const __nv_bfloat16* Vb = Vg + base;

    int tid = threadIdx.x;
    int lane = tid & 31, w = tid >> 5;
    int g = lane >> 2, t4 = lane & 3;
    int wr = w * 16;

    auto loadKV = [&](int st, int s0) {
        #pragma unroll
        for (int j = 0; j < 2; j++) {
            int c = tid + j * 256;
            int row = c >> 3;
            int cc = (c & 7) * 8;
            cp16(&Ks[st][row * KVW + cc], Kb + (long)(s0 + row) * HS_ + cc);
            cp16(&Vs[st][row * KVW + cc], Vb + (long)(s0 + row) * HS_ + cc);
        }
    };

    unsigned Qa[4][4];
    {
        const __nv_bfloat16* q0p = Qb + (long)(q0 + wr + g) * HS_;
        const __nv_bfloat16* q1p = q0p + 8 * HS_;
        #pragma unroll
        for (int c = 0; c < 4; c++) {
            Qa[c][0] = *reinterpret_cast<const unsigned*>(&q0p[c * 16 + 2 * t4]);
            Qa[c][1] = *reinterpret_cast<const unsigned*>(&q1p[c * 16 + 2 * t4]);
            Qa[c][2] = *reinterpret_cast<const unsigned*>(&q0p[c * 16 + 8 + 2 * t4]);
            Qa[c][3] = *reinterpret_cast<const unsigned*>(&q1p[c * 16 + 8 + 2 * t4]);
        }
    }

    float Oacc[8][4];
    #pragma unroll
    for (int i = 0; i < 8; i++)
        #pragma unroll
        for (int j = 0; j < 4; j++) Oacc[i][j] = 0.f;
    float m0 = -1e30f, m1 = -1e30f, l0 = 0.f, l1 = 0.f;

    int nT = causal ? (q0 / 64 + 2) : (T_ / 64);

    loadKV(0, 0);
    CP_COMMIT();

    int lmj = lane >> 3, lmt = lane & 7;
    int vt_off = ((lmj & 1) * 8 + lmt) * KVW + (lmj >> 1) * 8;          // V (trans)
    int kt_row = (lane & 7) + 8 * (lane >> 4);                          // K (non-trans)
    int kt_add = ((lane >> 3) & 1) * 8;

    for (int it = 0; it < nT; it++) {
        int s = it & 1;
        int s0 = it * 64;
        CP_WAIT(0);
        __syncthreads();
        if (it + 1 < nT) {
            loadKV(s ^ 1, (it + 1) * 64);
            CP_COMMIT();
        }

        unsigned kbase = sm_u32(&Ks[s][0]);
        unsigned vbase = sm_u32(&Vs[s][0]);

        float S[8][4];
        #pragma unroll
        for (int nf = 0; nf < 8; nf++)
            #pragma unroll
            for (int j = 0; j < 4; j++) S[nf][j] = 0.f;

        #pragma unroll
        for (int c = 0; c < 4; c++) {
            #pragma unroll
            for (int nfp = 0; nfp < 4; nfp++) {
                unsigned r0, r1, r2, r3;
                unsigned addr = kbase + (unsigned)(((nfp * 16 + kt_row) * KVW + c * 16 + kt_add) * 2);
                asm volatile(
                    "ldmatrix.sync.aligned.m8n8.x4.shared.b16 {%0,%1,%2,%3}, [%4];"
                    : "=r"(r0), "=r"(r1), "=r"(r2), "=r"(r3) : "r"(addr));
                mma_bf16(S[2 * nfp],     Qa[c], r0, r1);
                mma_bf16(S[2 * nfp + 1], Qa[c], r2, r3);
            }
        }

        if (causal && (s0 + 63 > q0 + wr)) {
            int r0g = q0 + wr + g;
            #pragma unroll
            for (int nf = 0; nf < 8; nf++) {
                int cbase = s0 + nf * 8 + 2 * t4;
                if (cbase     > r0g)     S[nf][0] = -1e30f;
                if (cbase + 1 > r0g)     S[nf][1] = -1e30f;
                if (cbase     > r0g + 8) S[nf][2] = -1e30f;
                if (cbase + 1 > r0g + 8) S[nf][3] = -1e30f;
            }
        }

        float tm0 = -1e30f, tm1 = -1e30f;
        #pragma unroll
        for (int nf = 0; nf < 8; nf++) {
            tm0 = fmaxf(tm0, fmaxf(S[nf][0], S[nf][1]));
            tm1 = fmaxf(tm1, fmaxf(S[nf][2], S[nf][3]));
        }
        tm0 = fmaxf(tm0, __shfl_xor_sync(0xffffffffu, tm0, 1));
        tm0 = fmaxf(tm0, __shfl_xor_sync(0xffffffffu, tm0, 2));
        tm1 = fmaxf(tm1, __shfl_xor_sync(0xffffffffu, tm1, 1));
        tm1 = fmaxf(tm1, __shfl_xor_sync(0xffffffffu, tm1, 2));

        float nm0 = fmaxf(m0, tm0), nm1 = fmaxf(m1, tm1);
        float f0 = ex2f((m0 - nm0) * CEXP), f1 = ex2f((m1 - nm1) * CEXP);

        float rs0 = 0.f, rs1 = 0.f;
        #pragma unroll
        for (int nf = 0; nf < 8; nf++) {
            S[nf][0] = ex2f((S[nf][0] - nm0) * CEXP);
            S[nf][1] = ex2f((S[nf][1] - nm0) * CEXP);
            S[nf][2] = ex2f((S[nf][2] - nm1) * CEXP);
            S[nf][3] = ex2f((S[nf][3] - nm1) * CEXP);
            rs0 += S[nf][0] + S[nf][1];
            rs1 += S[nf][2] + S[nf][3];
        }
        rs0 += __shfl_xor_sync(0xffffffffu, rs0, 1);
        rs0 += __shfl_xor_sync(0xffffffffu, rs0, 2);
        rs1 += __shfl_xor_sync(0xffffffffu, rs1, 1);
        rs1 += __shfl_xor_sync(0xffffffffu, rs1, 2);

        l0 = l0 * f0 + rs0;
        l1 = l1 * f1 + rs1;
        m0 = nm0; m1 = nm1;

        #pragma unroll
        for (int nf = 0; nf < 8; nf++) {
            Oacc[nf][0] *= f0; Oacc[nf][1] *= f0;
            Oacc[nf][2] *= f1; Oacc[nf][3] *= f1;
        }

        #pragma unroll
        for (int c = 0; c < 4; c++) {
            unsigned a4[4];
            a4[0] = packbf(S[2 * c][0],     S[2 * c][1]);
            a4[1] = packbf(S[2 * c][2],     S[2 * c][3]);
            a4[2] = packbf(S[2 * c + 1][0], S[2 * c + 1][1]);
            a4[3] = packbf(S[2 * c + 1][2], S[2 * c + 1][3]);
            #pragma unroll
            for (int gi = 0; gi < 4; gi++) {
                unsigned r0, r1, r2, r3;
                unsigned addr = vbase + (unsigned)((c * 16 * KVW + gi * 16 + vt_off) * 2);
                asm volatile(
                    "ldmatrix.sync.aligned.m8n8.x4.trans.shared.b16 {%0,%1,%2,%3}, [%4];"
                    : "=r"(r0), "=r"(r1), "=r"(r2), "=r"(r3) : "r"(addr));
                mma_bf16(Oacc[2 * gi],     a4, r0, r1);
                mma_bf16(Oacc[2 * gi + 1], a4, r2, r3);
            }
        }
    }

    float inv0 = 1.f / l0, inv1 = 1.f / l1;
    __nv_bfloat16* o0 = Out + ((long)b * T_ + q0 + wr + g) * C_ + h * HS_;
    __nv_bfloat16* o1 = Out + ((long)b * T_ + q0 + wr + g + 8) * C_ + h * HS_;
    #pragma unroll
    for (int nf = 0; nf < 8; nf++) {
        int c = nf * 8 + 2 * t4;
        *reinterpret_cast<unsigned*>(&o0[c]) = packbf(Oacc[nf][0] * inv0, Oacc[nf][1] * inv0);
        *reinterpret_cast<unsigned*>(&o1[c]) = packbf(Oacc[nf][2] * inv1, Oacc[nf][3] * inv1);
    }
}

// ---------------- orchestration ----------------
extern "C" void kernel_launch(void* const* d_in, const int* in_sizes, int n_in,
                              void* d_out, int out_size)
{
    const float* hidden = (const float*)d_in[0];
    const float* target = (const float*)d_in[1];
    const float* Wq_s = (const float*)d_in[2];
    const float* Wk_s = (const float*)d_in[3];
    const float* Wv_s = (const float*)d_in[4];
    const float* Wo_s = (const float*)d_in[5];
    const float* bo_s = (const float*)d_in[6];
    const float* Wq_x = (const float*)d_in[7];
    const float* Wk_x = (const float*)d_in[8];
    const float* Wv_x = (const float*)d_in[9];
    const float* Wo_x = (const float*)d_in[10];
    const float* bo_x = (const float*)d_in[11];
    const float* W1 = (const float*)d_in[12];
    const float* b1 = (const float*)d_in[13];
    const float* W2 = (const float*)d_in[14];
    const float* b2 = (const float*)d_in[15];
    const float* g1 = (const float*)d_in[16];
    const float* g2 = (const float*)d_in[17];
    const float* g3 = (const float*)d_in[18];
    const float* g4 = (const float*)d_in[19];

    float* t = (float*)d_out;

    __nv_bfloat16 *xnb, *hnb, *qb, *kb, *vb, *attnb, *ffb, *wb;
    cudaGetSymbolAddress((void**)&xnb, g_xnb);
    cudaGetSymbolAddress((void**)&hnb, g_hnb);
    cudaGetSymbolAddress((void**)&qb, g_q);
    cudaGetSymbolAddress((void**)&kb, g_k);
    cudaGetSymbolAddress((void**)&vb, g_v);
    cudaGetSymbolAddress((void**)&attnb, g_attnb);
    cudaGetSymbolAddress((void**)&ffb, g_ffb);
    cudaGetSymbolAddress((void**)&wb, g_wb);

    cudaFuncSetAttribute(gemm_qkv_bf, cudaFuncAttributeMaxDynamicSharedMemorySize, QKV_SMEM);
    cudaFuncSetAttribute(gemm_bf<2>, cudaFuncAttributeMaxDynamicSharedMemorySize, QKV_SMEM);
    cudaFuncSetAttribute(gemm_bf<1>, cudaFuncAttributeMaxDynamicSharedMemorySize, QKV_SMEM);
    const int smem2 = (3 * 128 * QASTR + 3 * 32 * (64 * 2 + 8)) * 2;   // 56832
    const int smem1 = (3 * 128 * QASTR + 3 * 32 * (64 * 1 + 8)) * 2;   // 44544

    // convert all weights to bf16 (QKV re-laid to [C][512])
    convw_k<<<dim3(256, NL, 10), 256>>>(
        Wq_s, Wk_s, Wv_s, Wo_s, Wq_x, Wk_x, Wv_x, Wo_x, W1, W2, wb);

    dim3 gQKV(12, T_ / 128, NB);             // 3 sels x 4 col-blocks, z=b
    dim3 gO(C_ / 64, BT_ / 128, 1);          // 256 CTAs (NI=1)
    dim3 gF1(FF_ / 128, BT_ / 128, 1);       // 256 CTAs (NI=2)
    dim3 gF2(C_ / 64, BT_ / 128, 1);         // 256 CTAs (NI=1)
    dim3 gFl(T_ / 128, BH_, 1);

    for (int l = 0; l < NL; l++) {
        const __nv_bfloat16* wl = wb + (long)l * WLAYER;

        // ======== masked self-attention ========
        const float* tcur = (l == 0) ? target : t;
        rmsnorm_k<<<BT_, 256>>>(tcur, g1 + (long)l * C_, xnb);

        gemm_qkv_bf<<<gQKV, 256, QKV_SMEM>>>(xnb, xnb, xnb,
            wl + WOFF_QS, wl + WOFF_KS, wl + WOFF_VS,
            qb, kb, vb, 4);

        flash_bf<<<gFl, 256>>>(qb, kb, vb, attnb, 1);

        gemm_bf<1><<<gO, 256, smem1>>>(C_,
            attnb, C_,
            wl + WOFF_OS, C_,
            bo_s + (long)l * C_,
            t, nullptr, (l == 0) ? target : nullptr,
            C_, (l == 0) ? 0 : 1, 0);

        // ======== cross-attention (dual rmsnorm + fused QKV) ========
        rmsnorm2_k<<<dim3(BT_, 2), 256>>>(
            hidden, g2 + (long)l * C_, hnb,
            t, g3 + (long)l * C_, xnb);

        gemm_qkv_bf<<<gQKV, 256, QKV_SMEM>>>(xnb, hnb, hnb,
            wl + WOFF_QX, wl + WOFF_KX, wl + WOFF_VX,
            qb, kb, vb, 4);

        flash_bf<<<gFl, 256>>>(qb, kb, vb, attnb, 0);

        gemm_bf<1><<<gO, 256, smem1>>>(C_,
            attnb, C_,
            wl + WOFF_OX, C_,
            bo_x + (long)l * C_,
            t, nullptr, nullptr,
            C_, 1, 0);

        // ======== GELU FFN ========
        rmsnorm_k<<<BT_, 256>>>(t, g4 + (long)l * C_, xnb);

        gemm_bf<2><<<gF1, 256, smem2>>>(C_,
            xnb, C_,
            wl + WOFF_W1, FF_,
            b1 + (long)l * FF_,
            nullptr, ffb, nullptr,
            FF_, 0, 1);

        gemm_bf<1><<<gF2, 256, smem1>>>(FF_,
            ffb, FF_,
            wl + WOFF_W2, C_,
            b2 + (long)l * C_,
            t, nullptr, nullptr,
            C_, 1, 0);
    }
}